// round 12
// baseline (speedup 1.0000x reference)
#include <cuda_runtime.h>
#include <cuda_fp16.h>
#include <cstdint>

#define NV 4096
#define F1 512
#define FH 256
#define NHEADS 4
#define F2 1024   // nhid * nheads
#define FO 256
#define NW (NV/32) // 128 bitmask words per row

#define PSROW 36   // gemm A tile row stride (words)
#define WROW  264  // gemm B tile row stride (words)
#define PST2  72   // attn P tile row stride (words; 64 used): 72%32==8
#define WBW   520  // attn Wh buf row stride (words; 512 used): 520%32==8

// ---------------- scratch (static device memory; no allocations) ------------
__device__ __align__(16) __half g_Wh1P[NHEADS * NV * FH];  // packed fp16 B-frag layout
__device__ __align__(16) float  g_h1[NV * F2];
__device__ __align__(16) __half g_Wh2P[NV * FO];
__device__ __align__(16) float  g_src1[NHEADS * NV];
__device__ __align__(16) float  g_dst1[NHEADS * NV];
__device__ __align__(16) float  g_src2[NV];
__device__ __align__(16) float  g_dst2[NV];
__device__ __align__(16) float  g_np[4 * NV * FO];       // L1 split numerators
__device__ __align__(16) float  g_lp[4 * NV];            // L1 split denominators
__device__ __align__(16) unsigned g_adjbits[NV * NW];    // 2 MB

// ---------------- helpers -----------------------------------------------------
__device__ __forceinline__ float tf32r(float x) {
    uint32_t u;
    asm("cvt.rna.tf32.f32 %0, %1;" : "=r"(u) : "f"(x));
    return __uint_as_float(u);
}
__device__ __forceinline__ uint32_t f2h2(float a, float b) {
    __half2 h = __floats2half2_rn(a, b);
    return *reinterpret_cast<uint32_t*>(&h);
}
__device__ __forceinline__ void mma_tf32(float* d, const uint32_t* a,
                                         uint32_t b0, uint32_t b1) {
    asm volatile(
        "mma.sync.aligned.m16n8k8.row.col.f32.tf32.tf32.f32 "
        "{%0,%1,%2,%3}, {%4,%5,%6,%7}, {%8,%9}, {%0,%1,%2,%3};"
        : "+f"(d[0]), "+f"(d[1]), "+f"(d[2]), "+f"(d[3])
        : "r"(a[0]), "r"(a[1]), "r"(a[2]), "r"(a[3]), "r"(b0), "r"(b1));
}
__device__ __forceinline__ void mma_f16(float* d, const uint32_t* a,
                                        uint32_t b0, uint32_t b1) {
    asm volatile(
        "mma.sync.aligned.m16n8k16.row.col.f32.f16.f16.f32 "
        "{%0,%1,%2,%3}, {%4,%5,%6,%7}, {%8,%9}, {%0,%1,%2,%3};"
        : "+f"(d[0]), "+f"(d[1]), "+f"(d[2]), "+f"(d[3])
        : "r"(a[0]), "r"(a[1]), "r"(a[2]), "r"(a[3]), "r"(b0), "r"(b1));
}
__device__ __forceinline__ void cp16(uint32_t saddr, const void* gptr) {
    asm volatile("cp.async.cg.shared.global [%0], [%1], 16;"
                 :: "r"(saddr), "l"(gptr));
}
__device__ __forceinline__ void cp_commit() {
    asm volatile("cp.async.commit_group;");
}
__device__ __forceinline__ void cp_wait0() {
    asm volatile("cp.async.wait_group 0;");
}
// packed fp16 layout: per 32-node block, 8 group-rows of 256*(4 halves);
// node jl -> group g = (jl>>4)*4 + ((jl&7)>>1), slot = (jl&1) + ((jl>>3)&1)*2
__device__ __forceinline__ size_t packed_base(int R) {
    int blk = R >> 5, jl = R & 31;
    int g = (jl >> 4) * 4 + ((jl & 7) >> 1);
    int slot = (jl & 1) + ((jl >> 3) & 1) * 2;
    return (size_t)blk * 8192 + (size_t)g * 1024 + slot;
}

// ---------------- K0: adjacency -> bitmask ----------------------------------
__global__ void adjbits_kernel(const int* __restrict__ adj) {
    int idx = blockIdx.x * blockDim.x + threadIdx.x;   // over NV*NV
    unsigned bit = (adj[idx] != 0) ? 1u : 0u;
    unsigned w = __ballot_sync(0xffffffffu, bit);
    if ((threadIdx.x & 31) == 0) g_adjbits[idx >> 5] = w;
}

// ---------------- K1: tf32 mma GEMM + fused src/dst projections --------------
// C packed fp16 only (attn B feed). src/dst computed from fp32 accumulators.
template <int ROWS>
__global__ void __launch_bounds__(512, 1)
gemm_tf32_kernel(const float* __restrict__ A, const float* __restrict__ B,
                 __half* __restrict__ Cp, const float* __restrict__ avec,
                 float* __restrict__ src, float* __restrict__ dst,
                 int K, long bStride, long cStride) {
    constexpr int MT = ROWS / 64;
    constexpr int TPR = 512 / ROWS;     // threads per A-row
    constexpr int AK  = 32 / TPR;       // A cols per thread
    extern __shared__ char smem[];
    float* As  = (float*)smem;                            // [2][ROWS*PSROW]
    float* Bs  = (float*)(smem + 2 * ROWS * PSROW * 4);   // [2][32*WROW]
    float* sa  = (float*)(smem + 2 * ROWS * PSROW * 4 + 2 * 32 * WROW * 4);
    float* lsm = sa + 2 * FH;                             // [ROWS][4][2]

    const int tid = threadIdx.x;
    const int wid = tid >> 5, lane = tid & 31;
    const int wr = wid >> 2, wc = wid & 3;
    const int b = blockIdx.y;
    const float* Bb = B + (size_t)b * bStride;
    __half* Cpb = Cp + (size_t)b * cStride;
    const float* av = avec + (size_t)b * 2 * FH;
    float* srcb = src + (size_t)b * NV;
    float* dstb = dst + (size_t)b * NV;
    const int i0 = blockIdx.x * ROWS;

    sa[tid] = av[tid];   // 512 threads load 2*FH floats

    const int arow = tid / TPR, ak0 = (tid % TPR) * AK;
    const int jrow = tid >> 4, fbase = (tid & 15) * 4;
    const int ar = lane >> 2, ak = lane & 3;

    float d[MT][8][4];
#pragma unroll
    for (int mt = 0; mt < MT; mt++)
#pragma unroll
        for (int nt = 0; nt < 8; nt++)
#pragma unroll
            for (int v = 0; v < 4; v++) d[mt][nt][v] = 0.f;

    const int NKT = K / 32;
    for (int kt = 0; kt < NKT; kt++) {
        const int bb = kt & 1;
        const int k0g = kt * 32;
        {
            const float* wp = Bb + (size_t)(k0g + jrow) * FH + fbase;
            float* bs = Bs + bb * 32 * WROW + jrow * WROW + fbase;
#pragma unroll
            for (int q = 0; q < 4; q++) {
                float4 v = *(const float4*)(wp + 64 * q);
                *(float4*)(bs + 64 * q) =
                    make_float4(tf32r(v.x), tf32r(v.y), tf32r(v.z), tf32r(v.w));
            }
            const float* ap = A + (size_t)(i0 + arow) * K + k0g + ak0;
            float* as = As + bb * ROWS * PSROW + arow * PSROW + ak0;
#pragma unroll
            for (int q = 0; q < AK / 4; q++) {
                float4 v = *(const float4*)(ap + 4 * q);
                *(float4*)(as + 4 * q) =
                    make_float4(tf32r(v.x), tf32r(v.y), tf32r(v.z), tf32r(v.w));
            }
        }
        __syncthreads();
        const float* pB = As + bb * ROWS * PSROW;
        const float* wB = Bs + bb * 32 * WROW;
#pragma unroll
        for (int kk = 0; kk < 4; kk++) {
            const int k0 = kk * 8;
            uint32_t a[MT][4];
#pragma unroll
            for (int mt = 0; mt < MT; mt++) {
                const float* pr = pB + (wr * 16 * MT + mt * 16 + ar) * PSROW + k0 + ak;
                a[mt][0] = __float_as_uint(pr[0]);
                a[mt][1] = __float_as_uint(pr[8 * PSROW]);
                a[mt][2] = __float_as_uint(pr[4]);
                a[mt][3] = __float_as_uint(pr[8 * PSROW + 4]);
            }
#pragma unroll
            for (int nt = 0; nt < 8; nt++) {
                const int n = wc * 64 + nt * 8 + ar;
                uint32_t b0 = __float_as_uint(wB[(k0 + ak) * WROW + n]);
                uint32_t b1 = __float_as_uint(wB[(k0 + ak + 4) * WROW + n]);
#pragma unroll
                for (int mt = 0; mt < MT; mt++)
                    mma_tf32(d[mt][nt], a[mt], b0, b1);
            }
        }
        __syncthreads();
    }
    // ---- epilogue: packed fp16 store + fused src/dst ----
#pragma unroll
    for (int mt = 0; mt < MT; mt++) {
        const int r0 = wr * 16 * MT + mt * 16 + ar;
        const int r1 = r0 + 8;
        const int R0 = i0 + r0, R1 = i0 + r1;
        const size_t pb0 = packed_base(R0), pb1 = packed_base(R1);
        float s10 = 0.f, s20 = 0.f, s11 = 0.f, s21 = 0.f;
#pragma unroll
        for (int nt = 0; nt < 8; nt++) {
            const int c = wc * 64 + nt * 8 + 2 * ak;
            float t0 = d[mt][nt][0], t1 = d[mt][nt][1];
            float t2 = d[mt][nt][2], t3 = d[mt][nt][3];
            Cpb[pb0 + (size_t)c * 4]       = __float2half_rn(t0);
            Cpb[pb0 + (size_t)(c + 1) * 4] = __float2half_rn(t1);
            Cpb[pb1 + (size_t)c * 4]       = __float2half_rn(t2);
            Cpb[pb1 + (size_t)(c + 1) * 4] = __float2half_rn(t3);
            s10 += t0 * sa[c] + t1 * sa[c + 1];
            s20 += t0 * sa[FH + c] + t1 * sa[FH + c + 1];
            s11 += t2 * sa[c] + t3 * sa[c + 1];
            s21 += t2 * sa[FH + c] + t3 * sa[FH + c + 1];
        }
        s10 += __shfl_down_sync(0xffffffffu, s10, 2);
        s10 += __shfl_down_sync(0xffffffffu, s10, 1);
        s20 += __shfl_down_sync(0xffffffffu, s20, 2);
        s20 += __shfl_down_sync(0xffffffffu, s20, 1);
        s11 += __shfl_down_sync(0xffffffffu, s11, 2);
        s11 += __shfl_down_sync(0xffffffffu, s11, 1);
        s21 += __shfl_down_sync(0xffffffffu, s21, 2);
        s21 += __shfl_down_sync(0xffffffffu, s21, 1);
        if (ak == 0) {
            lsm[r0 * 8 + wc * 2]     = s10;
            lsm[r0 * 8 + wc * 2 + 1] = s20;
            lsm[r1 * 8 + wc * 2]     = s11;
            lsm[r1 * 8 + wc * 2 + 1] = s21;
        }
    }
    __syncthreads();
    if (tid < ROWS) {
        float s1 = lsm[tid*8] + lsm[tid*8+2] + lsm[tid*8+4] + lsm[tid*8+6];
        float s2 = lsm[tid*8+1] + lsm[tid*8+3] + lsm[tid*8+5] + lsm[tid*8+7];
        srcb[i0 + tid] = s1;
        dstb[i0 + tid] = s2;
    }
}

#define GEMM_SMEM(R) (2 * (R) * PSROW * 4 + 2 * 32 * WROW * 4 + 512 * 4 + (R) * 8 * 4)

// ---------------- K3: fp16 mma fused attention, KT=128 per phase -------------
// 128x256 tile, 512 threads, 16 warps (4x4), per-SMSP phase stagger,
// 128 neighbors per barrier (4 adj words, 128 MMA/warp, 32 exp/thread).
// 2-buffer cp.async depth-1 (phase >> cp latency).
#define ATTN_SMEM (2 * 128 * PST2 * 4 + 2 * 32 * WBW * 4 + 512 * 4)

template <int NSPLIT>
__global__ void __launch_bounds__(512, 1)
attn_kernel() {
    extern __shared__ char smem[];
    float* Ps    = (float*)smem;                          // [2][128*PST2]
    float* Whs   = (float*)(smem + 2 * 128 * PST2 * 4);   // [2][32*WBW]
    float* lpart = (float*)(smem + 2 * 128 * PST2 * 4 + 2 * 32 * WBW * 4);
    const uint32_t whs_s = (uint32_t)__cvta_generic_to_shared(Whs);

    const int tid = threadIdx.x;
    const int wid = tid >> 5, lane = tid & 31;
    const int wr = wid >> 2, wc = wid & 3;
    const int i0 = blockIdx.x * 128;
    const bool mmaFirst = ((wid >> 2) & 1) != 0;   // per-SMSP 2/2 split

    const __half* WhP; const float* srcT; const float* dR;
    int jbase, NKT;
    if (NSPLIT > 1) {
        WhP = g_Wh2P; srcT = g_src2; dR = g_dst2;
        jbase = blockIdx.y * (NV / NSPLIT);
        NKT = (NV / NSPLIT) / 128;
    } else {
        const int b = blockIdx.z;
        WhP = g_Wh1P + (size_t)b * NV * FH;
        srcT = g_src1 + b * NV; dR = g_dst1 + b * NV;
        jbase = 0; NKT = NV / 128;
    }

    const int prow = tid >> 2;          // 0..127
    const int q_   = tid & 3;
    const float si = srcT[i0 + prow];
    const unsigned* adjrow = g_adjbits + (size_t)(i0 + prow) * NW + (jbase >> 5);
    const int ar = lane >> 2, ak = lane & 3;

    // cp.async mapping: 32 group-rows; thread -> (G = tid>>4, chunk (tid&15)*64 halves)
    const __half* wsrc0 = WhP + ((size_t)(jbase >> 5) + (tid >> 7)) * 8192 +
                          (size_t)((tid >> 4) & 7) * 1024 + (size_t)(tid & 15) * 64;
    const uint32_t wdst0 = whs_s +
                           (uint32_t)((tid >> 4) * WBW + (tid & 15) * 32) * 4u;

    float d[2][8][4];
#pragma unroll
    for (int mt = 0; mt < 2; mt++)
#pragma unroll
        for (int nt = 0; nt < 8; nt++)
#pragma unroll
            for (int v = 0; v < 4; v++) d[mt][nt][v] = 0.f;
    float lsum = 0.f;

    const int kb_ = (q_ < 2) ? 4 * q_ : 4 * q_ + 8;   // 0,4,16,20
    const int s_  = prow & 7;

#define COMPUTE_P(kt_, pbuf_)                                                 \
    {                                                                         \
        uint2* pr_ = (uint2*)((pbuf_) + prow * PST2);                         \
        _Pragma("unroll")                                                     \
        for (int h_ = 0; h_ < 4; h_++) {                                      \
            const int j0_ = jbase + (kt_) * 128 + 32 * h_;                    \
            const unsigned aw_ = adjrow[4 * (kt_) + h_];                      \
            float4 dv1 = *(const float4*)(dR + j0_ + kb_);                    \
            float4 dv2 = *(const float4*)(dR + j0_ + kb_ + 8);                \
            float dd_[8] = {dv1.x, dv1.y, dv1.z, dv1.w,                       \
                            dv2.x, dv2.y, dv2.z, dv2.w};                      \
            float p_[8];                                                      \
            _Pragma("unroll")                                                 \
            for (int u_ = 0; u_ < 8; u_++) {                                  \
                float e_ = si + dd_[u_];                                      \
                e_ = fmaxf(e_, 0.2f * e_);                                    \
                float pp_ = __expf(e_);                                       \
                pp_ = fminf(pp_, 65000.f);                                    \
                const int bit_ = kb_ + ((u_ < 4) ? u_ : u_ + 4);              \
                pp_ = ((aw_ >> bit_) & 1u) ? pp_ : 0.f;                       \
                lsum += pp_;                                                  \
                p_[u_] = pp_;                                                 \
            }                                                                 \
            const int g0_ = 2 * q_;                                           \
            pr_[8 * h_ + (g0_ ^ s_)] =                                        \
                make_uint2(f2h2(p_[0], p_[1]), f2h2(p_[4], p_[5]));           \
            pr_[8 * h_ + ((g0_ + 1) ^ s_)] =                                  \
                make_uint2(f2h2(p_[2], p_[3]), f2h2(p_[6], p_[7]));           \
        }                                                                     \
    }

#define ISSUE_WH(kt_, buf_)                                                   \
    {                                                                         \
        const __half* wp_ = wsrc0 + (size_t)(kt_) * 32768;                    \
        const uint32_t wd_ = wdst0 + (uint32_t)(buf_) * (32u * WBW * 4u);     \
        _Pragma("unroll")                                                     \
        for (int q2_ = 0; q2_ < 8; q2_++)                                     \
            cp16(wd_ + q2_ * 16u, wp_ + q2_ * 8);                             \
    }

#define PREP_STEP(kt_)                                                        \
    {                                                                         \
        if ((kt_) + 1 < NKT) { ISSUE_WH((kt_) + 1, ((kt_) + 1) & 1); }        \
        cp_commit();                                                          \
        if ((kt_) + 1 < NKT) {                                                \
            COMPUTE_P((kt_) + 1, Ps + (((kt_) + 1) & 1) * 128 * PST2);        \
        }                                                                     \
    }

#define MMA_STEP(kt_)                                                         \
    {                                                                         \
        const float* pB = Ps + ((kt_) & 1) * 128 * PST2;                      \
        const float* wB = Whs + ((kt_) & 1) * 32 * WBW;                       \
        _Pragma("unroll")                                                     \
        for (int kk = 0; kk < 8; kk++) {                                      \
            const int gi_ = kk * 4 + ak;                                      \
            const int idx_ = (gi_ & 24) | ((gi_ & 7) ^ ar);                   \
            uint32_t a[2][4];                                                 \
            _Pragma("unroll")                                                 \
            for (int mt = 0; mt < 2; mt++) {                                  \
                const int row_ = wr * 32 + mt * 16 + ar;                      \
                uint2 u_ = ((const uint2*)(pB + row_ * PST2))[idx_];          \
                uint2 v_ = ((const uint2*)(pB + (row_ + 8) * PST2))[idx_];    \
                a[mt][0] = u_.x; a[mt][1] = v_.x;                             \
                a[mt][2] = u_.y; a[mt][3] = v_.y;                             \
            }                                                                 \
            _Pragma("unroll")                                                 \
            for (int nt = 0; nt < 8; nt++) {                                  \
                const int n = wc * 64 + nt * 8 + ar;                          \
                uint2 b_ = ((const uint2*)(wB + gi_ * WBW))[n];               \
                _Pragma("unroll")                                             \
                for (int mt = 0; mt < 2; mt++)                                \
                    mma_f16(d[mt][nt], a[mt], b_.x, b_.y);                    \
            }                                                                 \
        }                                                                     \
    }

    // ---- prologue ----
    ISSUE_WH(0, 0); cp_commit();
    COMPUTE_P(0, Ps);

    for (int kt = 0; kt < NKT; kt++) {
        cp_wait0();          // Wh(kt) complete (per-thread)
        __syncthreads();     // visibility; prev MMA reads done
        if (mmaFirst) {
            MMA_STEP(kt);
            PREP_STEP(kt);
        } else {
            PREP_STEP(kt);
            MMA_STEP(kt);
        }
    }
    __syncthreads();
    lpart[tid] = lsum;       // lpart[prow*4 + q]
    __syncthreads();

    if (NSPLIT > 1) {
        float* np = g_np + (size_t)blockIdx.y * NV * FO;
#pragma unroll
        for (int mt = 0; mt < 2; mt++) {
            const int r0 = wr * 32 + mt * 16 + ar;
            const int r1 = r0 + 8;
#pragma unroll
            for (int nt = 0; nt < 8; nt++) {
                const int c = wc * 64 + nt * 8 + 2 * ak;
                *(float2*)(np + (size_t)(i0 + r0) * FO + c) = make_float2(d[mt][nt][0], d[mt][nt][1]);
                *(float2*)(np + (size_t)(i0 + r1) * FO + c) = make_float2(d[mt][nt][2], d[mt][nt][3]);
            }
        }
        if (tid < 128) {
            float l = lpart[tid * 4] + lpart[tid * 4 + 1] +
                      lpart[tid * 4 + 2] + lpart[tid * 4 + 3];
            g_lp[blockIdx.y * NV + i0 + tid] = l;
        }
    } else {
        float* out = g_h1;
        const int coloff = blockIdx.z * FH;
#pragma unroll
        for (int mt = 0; mt < 2; mt++) {
            const int r0 = wr * 32 + mt * 16 + ar;
            const int r1 = r0 + 8;
            const float l0 = lpart[r0*4] + lpart[r0*4+1] + lpart[r0*4+2] + lpart[r0*4+3];
            const float l1 = lpart[r1*4] + lpart[r1*4+1] + lpart[r1*4+2] + lpart[r1*4+3];
            const float rl0 = 1.0f / l0, rl1 = 1.0f / l1;
#pragma unroll
            for (int nt = 0; nt < 8; nt++) {
                const int c = coloff + wc * 64 + nt * 8 + 2 * ak;
                float o0 = d[mt][nt][0] * rl0, o1 = d[mt][nt][1] * rl0;
                float o2 = d[mt][nt][2] * rl1, o3 = d[mt][nt][3] * rl1;
                o0 = o0 > 0.f ? o0 : (__expf(o0) - 1.0f);
                o1 = o1 > 0.f ? o1 : (__expf(o1) - 1.0f);
                o2 = o2 > 0.f ? o2 : (__expf(o2) - 1.0f);
                o3 = o3 > 0.f ? o3 : (__expf(o3) - 1.0f);
                *(float2*)(out + (size_t)(i0 + r0) * F2 + c) = make_float2(o0, o1);
                *(float2*)(out + (size_t)(i0 + r1) * F2 + c) = make_float2(o2, o3);
            }
        }
    }
#undef COMPUTE_P
#undef ISSUE_WH
#undef PREP_STEP
#undef MMA_STEP
}

// ---------------- K4: combine 4 split partials (layer 1 epilogue) ------------
__global__ void combine_kernel(float* __restrict__ out) {
    const int i = blockIdx.x;
    const int c = threadIdx.x;
    float l = 0.f, n = 0.f;
#pragma unroll
    for (int s = 0; s < 4; s++) {
        l += g_lp[s * NV + i];
        n += g_np[(size_t)s * NV * FO + (size_t)i * FO + c];
    }
    out[(size_t)i * FO + c] = n / l;
}

// ---------------- launch -----------------------------------------------------
extern "C" void kernel_launch(void* const* d_in, const int* in_sizes, int n_in,
                              void* d_out, int out_size) {
    (void)in_sizes; (void)n_in; (void)out_size;
    const float* x   = (const float*)d_in[0];
    const int*   adj = (const int*)d_in[1];
    const float* W1  = (const float*)d_in[2];
    const float* a1  = (const float*)d_in[3];
    const float* W2  = (const float*)d_in[4];
    const float* a2  = (const float*)d_in[5];
    float* out = (float*)d_out;

    static int inited = 0;
    if (!inited) {
        cudaFuncSetAttribute(gemm_tf32_kernel<128>,
            cudaFuncAttributeMaxDynamicSharedMemorySize, GEMM_SMEM(128));
        cudaFuncSetAttribute(gemm_tf32_kernel<64>,
            cudaFuncAttributeMaxDynamicSharedMemorySize, GEMM_SMEM(64));
        cudaFuncSetAttribute(attn_kernel<1>,
            cudaFuncAttributeMaxDynamicSharedMemorySize, ATTN_SMEM);
        cudaFuncSetAttribute(attn_kernel<4>,
            cudaFuncAttributeMaxDynamicSharedMemorySize, ATTN_SMEM);
        inited = 1;
    }

    __half* Wh1pp; cudaGetSymbolAddress((void**)&Wh1pp, g_Wh1P);
    __half* Wh2pp; cudaGetSymbolAddress((void**)&Wh2pp, g_Wh2P);
    float*  h1p;   cudaGetSymbolAddress((void**)&h1p,   g_h1);
    float*  src1p; cudaGetSymbolAddress((void**)&src1p, g_src1);
    float*  dst1p; cudaGetSymbolAddress((void**)&dst1p, g_dst1);
    float*  src2p; cudaGetSymbolAddress((void**)&src2p, g_src2);
    float*  dst2p; cudaGetSymbolAddress((void**)&dst2p, g_dst2);

    adjbits_kernel<<<(NV * NV) / 256, 256>>>(adj);
    gemm_tf32_kernel<128><<<dim3(NV / 128, NHEADS), 512, GEMM_SMEM(128)>>>(
        x, W1, Wh1pp, a1, src1p, dst1p, F1, (long)F1 * FH, (long)NV * FH);
    attn_kernel<1><<<dim3(NV / 128, 1, NHEADS), 512, ATTN_SMEM>>>();
    gemm_tf32_kernel<64><<<dim3(NV / 64, 1), 512, GEMM_SMEM(64)>>>(
        h1p, W2, Wh2pp, a2, src2p, dst2p, F2, 0L, 0L);
    attn_kernel<4><<<dim3(NV / 128, 4), 512, ATTN_SMEM>>>();
    combine_kernel<<<NV, 256>>>(out);
}

// round 14
// speedup vs baseline: 1.2138x; 1.2138x over previous
#include <cuda_runtime.h>
#include <cuda_fp16.h>
#include <cstdint>

#define NV 4096
#define F1 512
#define FH 256
#define NHEADS 4
#define F2 1024   // nhid * nheads
#define FO 256
#define NW (NV/32) // 128 bitmask words per row

#define PSROW 36   // gemm A tile row stride (words)
#define WROW  264  // gemm B tile row stride (words): 264%32==8
#define PSTW  40   // attn P tile row stride (words; 32 used), swizzled groups
#define WBW   520  // attn Wh buf row stride (words; 512 used): 520%32==8

// ---------------- scratch (static device memory; no allocations) ------------
__device__ __align__(16) __half g_Wh1P[NHEADS * NV * FH];  // packed fp16 B-frag layout
__device__ __align__(16) float  g_h1[NV * F2];
__device__ __align__(16) __half g_Wh2P[NV * FO];
__device__ __align__(16) float  g_src1[NHEADS * NV];
__device__ __align__(16) float  g_dst1[NHEADS * NV];
__device__ __align__(16) float  g_src2[NV];
__device__ __align__(16) float  g_dst2[NV];
__device__ __align__(16) float  g_np[4 * NV * FO];       // L1 split numerators
__device__ __align__(16) float  g_lp[4 * NV];            // L1 split denominators
__device__ __align__(16) unsigned g_adjbits[NV * NW];    // 2 MB

// ---------------- helpers -----------------------------------------------------
__device__ __forceinline__ float tf32r(float x) {
    uint32_t u;
    asm("cvt.rna.tf32.f32 %0, %1;" : "=r"(u) : "f"(x));
    return __uint_as_float(u);
}
__device__ __forceinline__ float4 tf32r4(float4 v) {
    return make_float4(tf32r(v.x), tf32r(v.y), tf32r(v.z), tf32r(v.w));
}
__device__ __forceinline__ uint32_t f2h2(float a, float b) {
    __half2 h = __floats2half2_rn(a, b);
    return *reinterpret_cast<uint32_t*>(&h);
}
__device__ __forceinline__ void mma_tf32(float* d, const uint32_t* a,
                                         uint32_t b0, uint32_t b1) {
    asm volatile(
        "mma.sync.aligned.m16n8k8.row.col.f32.tf32.tf32.f32 "
        "{%0,%1,%2,%3}, {%4,%5,%6,%7}, {%8,%9}, {%0,%1,%2,%3};"
        : "+f"(d[0]), "+f"(d[1]), "+f"(d[2]), "+f"(d[3])
        : "r"(a[0]), "r"(a[1]), "r"(a[2]), "r"(a[3]), "r"(b0), "r"(b1));
}
__device__ __forceinline__ void mma_f16(float* d, const uint32_t* a,
                                        uint32_t b0, uint32_t b1) {
    asm volatile(
        "mma.sync.aligned.m16n8k16.row.col.f32.f16.f16.f32 "
        "{%0,%1,%2,%3}, {%4,%5,%6,%7}, {%8,%9}, {%0,%1,%2,%3};"
        : "+f"(d[0]), "+f"(d[1]), "+f"(d[2]), "+f"(d[3])
        : "r"(a[0]), "r"(a[1]), "r"(a[2]), "r"(a[3]), "r"(b0), "r"(b1));
}
__device__ __forceinline__ void cp16(uint32_t saddr, const void* gptr) {
    asm volatile("cp.async.cg.shared.global [%0], [%1], 16;"
                 :: "r"(saddr), "l"(gptr));
}
__device__ __forceinline__ void cp_commit() {
    asm volatile("cp.async.commit_group;");
}
__device__ __forceinline__ void cp_wait1() {
    asm volatile("cp.async.wait_group 1;");
}
// packed fp16 layout: per 32-node block, 8 group-rows of 256*(4 halves);
// node jl -> group g = (jl>>4)*4 + ((jl&7)>>1), slot = (jl&1) + ((jl>>3)&1)*2
__device__ __forceinline__ size_t packed_base(int R) {
    int blk = R >> 5, jl = R & 31;
    int g = (jl >> 4) * 4 + ((jl & 7) >> 1);
    int slot = (jl & 1) + ((jl >> 3) & 1) * 2;
    return (size_t)blk * 8192 + (size_t)g * 1024 + slot;
}

// ---------------- K0: adjacency -> bitmask ----------------------------------
__global__ void adjbits_kernel(const int* __restrict__ adj) {
    int idx = blockIdx.x * blockDim.x + threadIdx.x;   // over NV*NV
    unsigned bit = (adj[idx] != 0) ? 1u : 0u;
    unsigned w = __ballot_sync(0xffffffffu, bit);
    if ((threadIdx.x & 31) == 0) g_adjbits[idx >> 5] = w;
}

// ---------------- K1: tf32 mma GEMM + fused src/dst, reg-prefetch pipeline ---
// RNA-rounded tf32 inputs (unbiased). Per iter: STS(kt) -> LDG(kt+1) -> sync
// -> MMA(kt); double-buffered, one sync/iter (LDG latency hidden under MMA).
// C written packed fp16 only (attn B feed). src/dst from fp32 accumulators.
template <int ROWS>
__global__ void __launch_bounds__(512, 1)
gemm_tf32_kernel(const float* __restrict__ A, const float* __restrict__ B,
                 __half* __restrict__ Cp, const float* __restrict__ avec,
                 float* __restrict__ src, float* __restrict__ dst,
                 int K, long bStride, long cStride) {
    constexpr int MT  = ROWS / 64;
    constexpr int TPR = 512 / ROWS;     // threads per A-row (4 or 8)
    constexpr int AK  = 32 / TPR;       // A cols per thread (8 or 4)
    extern __shared__ char smem[];
    float* As  = (float*)smem;                            // [2][ROWS*PSROW]
    float* Bs  = (float*)(smem + 2 * ROWS * PSROW * 4);   // [2][32*WROW]
    float* sa  = (float*)(smem + 2 * ROWS * PSROW * 4 + 2 * 32 * WROW * 4);
    float* lsm = sa + 2 * FH;                             // [ROWS][8]

    const int tid = threadIdx.x;
    const int wid = tid >> 5, lane = tid & 31;
    const int wr = wid >> 2, wc = wid & 3;
    const int b = blockIdx.y;
    const float* Bb = B + (size_t)b * bStride;
    __half* Cpb = Cp + (size_t)b * cStride;
    const float* av = avec + (size_t)b * 2 * FH;
    float* srcb = src + (size_t)b * NV;
    float* dstb = dst + (size_t)b * NV;
    const int i0 = blockIdx.x * ROWS;

    sa[tid] = av[tid];   // 512 threads load 2*FH floats

    const int arow = tid / TPR, ak0 = (tid % TPR) * AK;
    const int jrow = tid >> 4, fbase = (tid & 15) * 4;
    const int ar = lane >> 2, ak = lane & 3;

    float d[MT][8][4];
#pragma unroll
    for (int mt = 0; mt < MT; mt++)
#pragma unroll
        for (int nt = 0; nt < 8; nt++)
#pragma unroll
            for (int v = 0; v < 4; v++) d[mt][nt][v] = 0.f;

    const int NKT = K / 32;
    float4 bReg[4];
    float4 aReg[AK / 4];

#define G_LOAD(kt_)                                                           \
    {                                                                         \
        const float* bp_ = Bb + (size_t)((kt_) * 32 + jrow) * FH + fbase;     \
        _Pragma("unroll")                                                     \
        for (int q_ = 0; q_ < 4; q_++) bReg[q_] = *(const float4*)(bp_ + 64 * q_); \
        const float* ap_ = A + (size_t)(i0 + arow) * K + (kt_) * 32 + ak0;    \
        _Pragma("unroll")                                                     \
        for (int q_ = 0; q_ < AK / 4; q_++) aReg[q_] = *(const float4*)(ap_ + 4 * q_); \
    }
#define G_STS(buf_)                                                           \
    {                                                                         \
        float* bs_ = Bs + (buf_) * 32 * WROW + jrow * WROW + fbase;           \
        _Pragma("unroll")                                                     \
        for (int q_ = 0; q_ < 4; q_++)                                        \
            *(float4*)(bs_ + 64 * q_) = tf32r4(bReg[q_]);                     \
        float* as_ = As + (buf_) * ROWS * PSROW + arow * PSROW + ak0;         \
        _Pragma("unroll")                                                     \
        for (int q_ = 0; q_ < AK / 4; q_++)                                   \
            *(float4*)(as_ + 4 * q_) = tf32r4(aReg[q_]);                      \
    }

    G_LOAD(0);
    for (int kt = 0; kt < NKT; kt++) {
        const int bb = kt & 1;
        G_STS(bb);
        if (kt + 1 < NKT) { G_LOAD(kt + 1); }
        __syncthreads();
        const float* pB = As + bb * ROWS * PSROW;
        const float* wB = Bs + bb * 32 * WROW;
#pragma unroll
        for (int kk = 0; kk < 4; kk++) {
            const int k0 = kk * 8;
            uint32_t a[MT][4];
#pragma unroll
            for (int mt = 0; mt < MT; mt++) {
                const float* pr = pB + (wr * 16 * MT + mt * 16 + ar) * PSROW + k0 + ak;
                a[mt][0] = __float_as_uint(pr[0]);
                a[mt][1] = __float_as_uint(pr[8 * PSROW]);
                a[mt][2] = __float_as_uint(pr[4]);
                a[mt][3] = __float_as_uint(pr[8 * PSROW + 4]);
            }
#pragma unroll
            for (int nt = 0; nt < 8; nt++) {
                const int n = wc * 64 + nt * 8 + ar;
                uint32_t b0 = __float_as_uint(wB[(k0 + ak) * WROW + n]);
                uint32_t b1 = __float_as_uint(wB[(k0 + ak + 4) * WROW + n]);
#pragma unroll
                for (int mt = 0; mt < MT; mt++)
                    mma_tf32(d[mt][nt], a[mt], b0, b1);
            }
        }
    }
#undef G_LOAD
#undef G_STS
    __syncthreads();
    // ---- epilogue: packed fp16 store + fused src/dst ----
#pragma unroll
    for (int mt = 0; mt < MT; mt++) {
        const int r0 = wr * 16 * MT + mt * 16 + ar;
        const int r1 = r0 + 8;
        const int R0 = i0 + r0, R1 = i0 + r1;
        const size_t pb0 = packed_base(R0), pb1 = packed_base(R1);
        float s10 = 0.f, s20 = 0.f, s11 = 0.f, s21 = 0.f;
#pragma unroll
        for (int nt = 0; nt < 8; nt++) {
            const int c = wc * 64 + nt * 8 + 2 * ak;
            float t0 = d[mt][nt][0], t1 = d[mt][nt][1];
            float t2 = d[mt][nt][2], t3 = d[mt][nt][3];
            Cpb[pb0 + (size_t)c * 4]       = __float2half_rn(t0);
            Cpb[pb0 + (size_t)(c + 1) * 4] = __float2half_rn(t1);
            Cpb[pb1 + (size_t)c * 4]       = __float2half_rn(t2);
            Cpb[pb1 + (size_t)(c + 1) * 4] = __float2half_rn(t3);
            s10 += t0 * sa[c] + t1 * sa[c + 1];
            s20 += t0 * sa[FH + c] + t1 * sa[FH + c + 1];
            s11 += t2 * sa[c] + t3 * sa[c + 1];
            s21 += t2 * sa[FH + c] + t3 * sa[FH + c + 1];
        }
        s10 += __shfl_down_sync(0xffffffffu, s10, 2);
        s10 += __shfl_down_sync(0xffffffffu, s10, 1);
        s20 += __shfl_down_sync(0xffffffffu, s20, 2);
        s20 += __shfl_down_sync(0xffffffffu, s20, 1);
        s11 += __shfl_down_sync(0xffffffffu, s11, 2);
        s11 += __shfl_down_sync(0xffffffffu, s11, 1);
        s21 += __shfl_down_sync(0xffffffffu, s21, 2);
        s21 += __shfl_down_sync(0xffffffffu, s21, 1);
        if (ak == 0) {
            lsm[r0 * 8 + wc * 2]     = s10;
            lsm[r0 * 8 + wc * 2 + 1] = s20;
            lsm[r1 * 8 + wc * 2]     = s11;
            lsm[r1 * 8 + wc * 2 + 1] = s21;
        }
    }
    __syncthreads();
    if (tid < ROWS) {
        float s1 = lsm[tid*8] + lsm[tid*8+2] + lsm[tid*8+4] + lsm[tid*8+6];
        float s2 = lsm[tid*8+1] + lsm[tid*8+3] + lsm[tid*8+5] + lsm[tid*8+7];
        srcb[i0 + tid] = s1;
        dstb[i0 + tid] = s2;
    }
}

#define GEMM_SMEM(R) (2 * (R) * PSROW * 4 + 2 * 32 * WROW * 4 + 512 * 4 + (R) * 8 * 4)

// ---------------- K3: fp16 mma fused attention, KT=64 per phase --------------
// (R11-proven structure) 128x256 tile, 512 threads, 16 warps (4x4),
// per-SMSP phase stagger, 64 neighbors/barrier, 3-buffer cp.async depth-2.
#define ATTN_SMEM (2 * 128 * PSTW * 4 + 3 * 16 * WBW * 4 + 512 * 4)

template <int NSPLIT>
__global__ void __launch_bounds__(512, 1)
attn_kernel() {
    extern __shared__ char smem[];
    float* Ps    = (float*)smem;                          // [2][128*PSTW]
    float* Whs   = (float*)(smem + 2 * 128 * PSTW * 4);   // [3][16*WBW]
    float* lpart = (float*)(smem + 2 * 128 * PSTW * 4 + 3 * 16 * WBW * 4);
    const uint32_t whs_s = (uint32_t)__cvta_generic_to_shared(Whs);

    const int tid = threadIdx.x;
    const int wid = tid >> 5, lane = tid & 31;
    const int wr = wid >> 2, wc = wid & 3;
    const int i0 = blockIdx.x * 128;
    const bool mmaFirst = ((wid >> 2) & 1) != 0;   // per-SMSP 2/2 split

    const __half* WhP; const float* srcT; const float* dR;
    int jbase, NKT;
    if (NSPLIT > 1) {
        WhP = g_Wh2P; srcT = g_src2; dR = g_dst2;
        jbase = blockIdx.y * (NV / NSPLIT);
        NKT = (NV / NSPLIT) / 64;
    } else {
        const int b = blockIdx.z;
        WhP = g_Wh1P + (size_t)b * NV * FH;
        srcT = g_src1 + b * NV; dR = g_dst1 + b * NV;
        jbase = 0; NKT = NV / 64;
    }

    const int prow = tid >> 2;          // 0..127
    const int q_   = tid & 3;
    const float si = srcT[i0 + prow];
    const unsigned* adjrow = g_adjbits + (size_t)(i0 + prow) * NW + (jbase >> 5);
    const int ar = lane >> 2, ak = lane & 3;

    // cp.async mapping: thread -> (group row tid>>5 of 16, chunk tid&31)
    const __half* wsrc0 = WhP + (size_t)(jbase >> 5) * 8192 +
                          (size_t)(tid >> 5) * 1024 + (size_t)(tid & 31) * 8;
    const uint32_t wdst0 = whs_s +
                           (uint32_t)((tid >> 5) * WBW + (tid & 31) * 4) * 4u;

    float d[2][8][4];
#pragma unroll
    for (int mt = 0; mt < 2; mt++)
#pragma unroll
        for (int nt = 0; nt < 8; nt++)
#pragma unroll
            for (int v = 0; v < 4; v++) d[mt][nt][v] = 0.f;
    float lsum = 0.f;

    const int kb_ = (q_ < 2) ? 4 * q_ : 4 * q_ + 8;   // 0,4,16,20
    const int s_  = prow & 7;

#define COMPUTE_P(kt_, pbuf_)                                                 \
    {                                                                         \
        uint2* pr_ = (uint2*)((pbuf_) + prow * PSTW);                         \
        _Pragma("unroll")                                                     \
        for (int h_ = 0; h_ < 2; h_++) {                                      \
            const int j0_ = jbase + (kt_) * 64 + 32 * h_;                     \
            const unsigned aw_ = adjrow[2 * (kt_) + h_];                      \
            float4 dv1 = *(const float4*)(dR + j0_ + kb_);                    \
            float4 dv2 = *(const float4*)(dR + j0_ + kb_ + 8);                \
            float dd_[8] = {dv1.x, dv1.y, dv1.z, dv1.w,                       \
                            dv2.x, dv2.y, dv2.z, dv2.w};                      \
            float p_[8];                                                      \
            _Pragma("unroll")                                                 \
            for (int u_ = 0; u_ < 8; u_++) {                                  \
                float e_ = si + dd_[u_];                                      \
                e_ = fmaxf(e_, 0.2f * e_);                                    \
                float pp_ = __expf(e_);                                       \
                pp_ = fminf(pp_, 65000.f);                                    \
                const int bit_ = kb_ + ((u_ < 4) ? u_ : u_ + 4);              \
                pp_ = ((aw_ >> bit_) & 1u) ? pp_ : 0.f;                       \
                lsum += pp_;                                                  \
                p_[u_] = pp_;                                                 \
            }                                                                 \
            const int g0_ = 2 * q_;                                           \
            pr_[8 * h_ + (g0_ ^ s_)] =                                        \
                make_uint2(f2h2(p_[0], p_[1]), f2h2(p_[4], p_[5]));           \
            pr_[8 * h_ + ((g0_ + 1) ^ s_)] =                                  \
                make_uint2(f2h2(p_[2], p_[3]), f2h2(p_[6], p_[7]));           \
        }                                                                     \
    }

#define ISSUE_WH(kt_, buf_)                                                   \
    {                                                                         \
        const __half* wp_ = wsrc0 + (size_t)(kt_) * 16384;                    \
        const uint32_t wd_ = wdst0 + (uint32_t)(buf_) * (16u * WBW * 4u);     \
        _Pragma("unroll")                                                     \
        for (int q2_ = 0; q2_ < 4; q2_++)                                     \
            cp16(wd_ + q2_ * 512u, wp_ + q2_ * 256);                          \
    }

#define PREP_STEP(kt_)                                                        \
    {                                                                         \
        if ((kt_) + 2 < NKT) { ISSUE_WH((kt_) + 2, ((kt_) + 2) % 3); }        \
        cp_commit();                                                          \
        if ((kt_) + 1 < NKT) {                                                \
            COMPUTE_P((kt_) + 1, Ps + (((kt_) + 1) & 1) * 128 * PSTW);        \
        }                                                                     \
    }

#define MMA_STEP(kt_)                                                         \
    {                                                                         \
        const float* pB = Ps + ((kt_) & 1) * 128 * PSTW;                      \
        const float* wB = Whs + ((kt_) % 3) * 16 * WBW;                       \
        _Pragma("unroll")                                                     \
        for (int kk = 0; kk < 4; kk++) {                                      \
            const int gi_ = kk * 4 + ak;                                      \
            const int idx_ = (gi_ & 8) | ((gi_ & 7) ^ ar);                    \
            uint32_t a[2][4];                                                 \
            _Pragma("unroll")                                                 \
            for (int mt = 0; mt < 2; mt++) {                                  \
                const int row_ = wr * 32 + mt * 16 + ar;                      \
                uint2 u_ = ((const uint2*)(pB + row_ * PSTW))[idx_];          \
                uint2 v_ = ((const uint2*)(pB + (row_ + 8) * PSTW))[idx_];    \
                a[mt][0] = u_.x; a[mt][1] = v_.x;                             \
                a[mt][2] = u_.y; a[mt][3] = v_.y;                             \
            }                                                                 \
            _Pragma("unroll")                                                 \
            for (int nt = 0; nt < 8; nt++) {                                  \
                const int n = wc * 64 + nt * 8 + ar;                          \
                uint2 b_ = ((const uint2*)(wB + gi_ * WBW))[n];               \
                _Pragma("unroll")                                             \
                for (int mt = 0; mt < 2; mt++)                                \
                    mma_f16(d[mt][nt], a[mt], b_.x, b_.y);                    \
            }                                                                 \
        }                                                                     \
    }

    // ---- prologue ----
    ISSUE_WH(0, 0); cp_commit();
    if (1 < NKT) { ISSUE_WH(1, 1); }
    cp_commit();
    COMPUTE_P(0, Ps);

    for (int kt = 0; kt < NKT; kt++) {
        cp_wait1();          // Wh(kt) complete (per-thread)
        __syncthreads();     // visibility; prev MMA reads done
        if (mmaFirst) {
            MMA_STEP(kt);
            PREP_STEP(kt);
        } else {
            PREP_STEP(kt);
            MMA_STEP(kt);
        }
    }
    __syncthreads();
    lpart[tid] = lsum;       // lpart[prow*4 + q]
    __syncthreads();

    if (NSPLIT > 1) {
        float* np = g_np + (size_t)blockIdx.y * NV * FO;
#pragma unroll
        for (int mt = 0; mt < 2; mt++) {
            const int r0 = wr * 32 + mt * 16 + ar;
            const int r1 = r0 + 8;
#pragma unroll
            for (int nt = 0; nt < 8; nt++) {
                const int c = wc * 64 + nt * 8 + 2 * ak;
                *(float2*)(np + (size_t)(i0 + r0) * FO + c) = make_float2(d[mt][nt][0], d[mt][nt][1]);
                *(float2*)(np + (size_t)(i0 + r1) * FO + c) = make_float2(d[mt][nt][2], d[mt][nt][3]);
            }
        }
        if (tid < 128) {
            float l = lpart[tid * 4] + lpart[tid * 4 + 1] +
                      lpart[tid * 4 + 2] + lpart[tid * 4 + 3];
            g_lp[blockIdx.y * NV + i0 + tid] = l;
        }
    } else {
        float* out = g_h1;
        const int coloff = blockIdx.z * FH;
#pragma unroll
        for (int mt = 0; mt < 2; mt++) {
            const int r0 = wr * 32 + mt * 16 + ar;
            const int r1 = r0 + 8;
            const float l0 = lpart[r0*4] + lpart[r0*4+1] + lpart[r0*4+2] + lpart[r0*4+3];
            const float l1 = lpart[r1*4] + lpart[r1*4+1] + lpart[r1*4+2] + lpart[r1*4+3];
            const float rl0 = 1.0f / l0, rl1 = 1.0f / l1;
#pragma unroll
            for (int nt = 0; nt < 8; nt++) {
                const int c = coloff + wc * 64 + nt * 8 + 2 * ak;
                float o0 = d[mt][nt][0] * rl0, o1 = d[mt][nt][1] * rl0;
                float o2 = d[mt][nt][2] * rl1, o3 = d[mt][nt][3] * rl1;
                o0 = o0 > 0.f ? o0 : (__expf(o0) - 1.0f);
                o1 = o1 > 0.f ? o1 : (__expf(o1) - 1.0f);
                o2 = o2 > 0.f ? o2 : (__expf(o2) - 1.0f);
                o3 = o3 > 0.f ? o3 : (__expf(o3) - 1.0f);
                *(float2*)(out + (size_t)(i0 + r0) * F2 + c) = make_float2(o0, o1);
                *(float2*)(out + (size_t)(i0 + r1) * F2 + c) = make_float2(o2, o3);
            }
        }
    }
#undef COMPUTE_P
#undef ISSUE_WH
#undef PREP_STEP
#undef MMA_STEP
}

// ---------------- K4: combine 4 split partials (layer 1 epilogue) ------------
__global__ void combine_kernel(float* __restrict__ out) {
    const int i = blockIdx.x;
    const int c = threadIdx.x;
    float l = 0.f, n = 0.f;
#pragma unroll
    for (int s = 0; s < 4; s++) {
        l += g_lp[s * NV + i];
        n += g_np[(size_t)s * NV * FO + (size_t)i * FO + c];
    }
    out[(size_t)i * FO + c] = n / l;
}

// ---------------- launch -----------------------------------------------------
extern "C" void kernel_launch(void* const* d_in, const int* in_sizes, int n_in,
                              void* d_out, int out_size) {
    (void)in_sizes; (void)n_in; (void)out_size;
    const float* x   = (const float*)d_in[0];
    const int*   adj = (const int*)d_in[1];
    const float* W1  = (const float*)d_in[2];
    const float* a1  = (const float*)d_in[3];
    const float* W2  = (const float*)d_in[4];
    const float* a2  = (const float*)d_in[5];
    float* out = (float*)d_out;

    static int inited = 0;
    if (!inited) {
        cudaFuncSetAttribute(gemm_tf32_kernel<128>,
            cudaFuncAttributeMaxDynamicSharedMemorySize, GEMM_SMEM(128));
        cudaFuncSetAttribute(gemm_tf32_kernel<64>,
            cudaFuncAttributeMaxDynamicSharedMemorySize, GEMM_SMEM(64));
        cudaFuncSetAttribute(attn_kernel<1>,
            cudaFuncAttributeMaxDynamicSharedMemorySize, ATTN_SMEM);
        cudaFuncSetAttribute(attn_kernel<4>,
            cudaFuncAttributeMaxDynamicSharedMemorySize, ATTN_SMEM);
        inited = 1;
    }

    __half* Wh1pp; cudaGetSymbolAddress((void**)&Wh1pp, g_Wh1P);
    __half* Wh2pp; cudaGetSymbolAddress((void**)&Wh2pp, g_Wh2P);
    float*  h1p;   cudaGetSymbolAddress((void**)&h1p,   g_h1);
    float*  src1p; cudaGetSymbolAddress((void**)&src1p, g_src1);
    float*  dst1p; cudaGetSymbolAddress((void**)&dst1p, g_dst1);
    float*  src2p; cudaGetSymbolAddress((void**)&src2p, g_src2);
    float*  dst2p; cudaGetSymbolAddress((void**)&dst2p, g_dst2);

    adjbits_kernel<<<(NV * NV) / 256, 256>>>(adj);
    gemm_tf32_kernel<128><<<dim3(NV / 128, NHEADS), 512, GEMM_SMEM(128)>>>(
        x, W1, Wh1pp, a1, src1p, dst1p, F1, (long)F1 * FH, (long)NV * FH);
    attn_kernel<1><<<dim3(NV / 128, 1, NHEADS), 512, ATTN_SMEM>>>();
    gemm_tf32_kernel<64><<<dim3(NV / 64, 1), 512, GEMM_SMEM(64)>>>(
        h1p, W2, Wh2pp, a2, src2p, dst2p, F2, 0L, 0L);
    attn_kernel<4><<<dim3(NV / 128, 4), 512, ATTN_SMEM>>>();
    combine_kernel<<<NV, 256>>>(out);
}

// round 15
// speedup vs baseline: 1.2706x; 1.0468x over previous
#include <cuda_runtime.h>
#include <cuda_fp16.h>
#include <cstdint>

#define NV 4096
#define F1 512
#define FH 256
#define NHEADS 4
#define F2 1024   // nhid * nheads
#define FO 256
#define NW (NV/32) // 128 bitmask words per row

#define PSROW 36   // gemm A tile row stride (words)
#define PSTW  40   // attn P tile row stride (words; 32 used), swizzled groups
#define WBW   520  // attn Wh buf row stride (words; 512 used): 520%32==8

// ---------------- scratch (static device memory; no allocations) ------------
__device__ __align__(16) __half g_Wh1P[NHEADS * NV * FH];  // packed fp16 B-frag layout
__device__ __align__(16) float  g_h1[NV * F2];
__device__ __align__(16) __half g_Wh2P[NV * FO];
__device__ __align__(16) float  g_src1[NHEADS * NV];
__device__ __align__(16) float  g_dst1[NHEADS * NV];
__device__ __align__(16) float  g_src2[NV];
__device__ __align__(16) float  g_dst2[NV];
__device__ __align__(16) float  g_srcp[2 * NV];          // GEMM2 col-split partials
__device__ __align__(16) float  g_dstp[2 * NV];
__device__ __align__(16) float  g_np[4 * NV * FO];       // L1 split numerators
__device__ __align__(16) float  g_lp[4 * NV];            // L1 split denominators
__device__ __align__(16) unsigned g_adjbits[NV * NW];    // 2 MB

// ---------------- helpers -----------------------------------------------------
__device__ __forceinline__ float tf32r(float x) {
    uint32_t u;
    asm("cvt.rna.tf32.f32 %0, %1;" : "=r"(u) : "f"(x));
    return __uint_as_float(u);
}
__device__ __forceinline__ float4 tf32r4(float4 v) {
    return make_float4(tf32r(v.x), tf32r(v.y), tf32r(v.z), tf32r(v.w));
}
__device__ __forceinline__ uint32_t f2h2(float a, float b) {
    __half2 h = __floats2half2_rn(a, b);
    return *reinterpret_cast<uint32_t*>(&h);
}
__device__ __forceinline__ void mma_tf32(float* d, const uint32_t* a,
                                         uint32_t b0, uint32_t b1) {
    asm volatile(
        "mma.sync.aligned.m16n8k8.row.col.f32.tf32.tf32.f32 "
        "{%0,%1,%2,%3}, {%4,%5,%6,%7}, {%8,%9}, {%0,%1,%2,%3};"
        : "+f"(d[0]), "+f"(d[1]), "+f"(d[2]), "+f"(d[3])
        : "r"(a[0]), "r"(a[1]), "r"(a[2]), "r"(a[3]), "r"(b0), "r"(b1));
}
__device__ __forceinline__ void mma_f16(float* d, const uint32_t* a,
                                        uint32_t b0, uint32_t b1) {
    asm volatile(
        "mma.sync.aligned.m16n8k16.row.col.f32.f16.f16.f32 "
        "{%0,%1,%2,%3}, {%4,%5,%6,%7}, {%8,%9}, {%0,%1,%2,%3};"
        : "+f"(d[0]), "+f"(d[1]), "+f"(d[2]), "+f"(d[3])
        : "r"(a[0]), "r"(a[1]), "r"(a[2]), "r"(a[3]), "r"(b0), "r"(b1));
}
__device__ __forceinline__ void cp16(uint32_t saddr, const void* gptr) {
    asm volatile("cp.async.cg.shared.global [%0], [%1], 16;"
                 :: "r"(saddr), "l"(gptr));
}
__device__ __forceinline__ void cp_commit() {
    asm volatile("cp.async.commit_group;");
}
__device__ __forceinline__ void cp_wait1() {
    asm volatile("cp.async.wait_group 1;");
}
// packed fp16 layout: per 32-node block, 8 group-rows of 256*(4 halves);
// node jl -> group g = (jl>>4)*4 + ((jl&7)>>1), slot = (jl&1) + ((jl>>3)&1)*2
__device__ __forceinline__ size_t packed_base(int R) {
    int blk = R >> 5, jl = R & 31;
    int g = (jl >> 4) * 4 + ((jl & 7) >> 1);
    int slot = (jl & 1) + ((jl >> 3) & 1) * 2;
    return (size_t)blk * 8192 + (size_t)g * 1024 + slot;
}

// ---------------- K0: adjacency -> bitmask ----------------------------------
__global__ void adjbits_kernel(const int* __restrict__ adj) {
    int idx = blockIdx.x * blockDim.x + threadIdx.x;   // over NV*NV
    unsigned bit = (adj[idx] != 0) ? 1u : 0u;
    unsigned w = __ballot_sync(0xffffffffu, bit);
    if ((threadIdx.x & 31) == 0) g_adjbits[idx >> 5] = w;
}

// ---------------- K1: tf32 mma GEMM + fused src/dst, reg-prefetch pipeline ---
// CSPLIT=1: blockIdx.y = head. CSPLIT=2: blockIdx.y = column half (GEMM2),
// src/dst written as per-half partials (combined by srccomb_kernel).
template <int ROWS, int CSPLIT>
__global__ void __launch_bounds__(512, 1)
gemm_tf32_kernel(const float* __restrict__ A, const float* __restrict__ B,
                 __half* __restrict__ Cp, const float* __restrict__ avec,
                 float* __restrict__ src, float* __restrict__ dst,
                 int K, long bStride, long cStride) {
    constexpr int MT  = ROWS / 64;
    constexpr int TPR = 512 / ROWS;       // threads per A-row (4 or 8)
    constexpr int AK  = 32 / TPR;         // A cols per thread (8 or 4)
    constexpr int NCOLS = 256 / CSPLIT;   // output cols per CTA
    constexpr int NT  = NCOLS / 32;       // n-tiles per warp (8 or 4)
    constexpr int BST = NCOLS + 8;        // B tile stride: =8 (mod 32)
    constexpr int BQ  = NCOLS / 64;       // B float4 loads per thread
    extern __shared__ char smem[];
    float* As  = (float*)smem;                            // [2][ROWS*PSROW]
    float* Bs  = (float*)(smem + 2 * ROWS * PSROW * 4);   // [2][32*BST]
    float* sa  = (float*)(smem + 2 * ROWS * PSROW * 4 + 2 * 32 * BST * 4);
    float* lsm = sa + 2 * FH;                             // [ROWS][8]

    const int tid = threadIdx.x;
    const int wid = tid >> 5, lane = tid & 31;
    const int wr = wid >> 2, wc = wid & 3;
    const int b  = (CSPLIT > 1) ? 0 : blockIdx.y;
    const int cs = (CSPLIT > 1) ? blockIdx.y : 0;
    const int coloff = cs * NCOLS;
    const float* Bb = B + (size_t)b * bStride;
    __half* Cpb = Cp + (size_t)b * cStride;
    const float* av = avec + (size_t)b * 2 * FH;
    float* srcb = src + (size_t)((CSPLIT > 1) ? cs : b) * NV;
    float* dstb = dst + (size_t)((CSPLIT > 1) ? cs : b) * NV;
    const int i0 = blockIdx.x * ROWS;

    sa[tid] = av[tid];   // 512 threads load 2*FH floats

    const int arow = tid / TPR, ak0 = (tid % TPR) * AK;
    const int jrow = tid >> 4, fbase = (tid & 15) * 4;
    const int ar = lane >> 2, ak = lane & 3;

    float d[MT][NT][4];
#pragma unroll
    for (int mt = 0; mt < MT; mt++)
#pragma unroll
        for (int nt = 0; nt < NT; nt++)
#pragma unroll
            for (int v = 0; v < 4; v++) d[mt][nt][v] = 0.f;

    const int NKT = K / 32;
    float4 bReg[BQ];
    float4 aReg[AK / 4];

#define G_LOAD(kt_)                                                           \
    {                                                                         \
        const float* bp_ = Bb + (size_t)((kt_) * 32 + jrow) * FH + coloff + fbase; \
        _Pragma("unroll")                                                     \
        for (int q_ = 0; q_ < BQ; q_++) bReg[q_] = *(const float4*)(bp_ + 64 * q_); \
        const float* ap_ = A + (size_t)(i0 + arow) * K + (kt_) * 32 + ak0;    \
        _Pragma("unroll")                                                     \
        for (int q_ = 0; q_ < AK / 4; q_++) aReg[q_] = *(const float4*)(ap_ + 4 * q_); \
    }
#define G_STS(buf_)                                                           \
    {                                                                         \
        float* bs_ = Bs + (buf_) * 32 * BST + jrow * BST + fbase;             \
        _Pragma("unroll")                                                     \
        for (int q_ = 0; q_ < BQ; q_++)                                       \
            *(float4*)(bs_ + 64 * q_) = tf32r4(bReg[q_]);                     \
        float* as_ = As + (buf_) * ROWS * PSROW + arow * PSROW + ak0;         \
        _Pragma("unroll")                                                     \
        for (int q_ = 0; q_ < AK / 4; q_++)                                   \
            *(float4*)(as_ + 4 * q_) = tf32r4(aReg[q_]);                      \
    }

    G_LOAD(0);
    for (int kt = 0; kt < NKT; kt++) {
        const int bb = kt & 1;
        G_STS(bb);
        if (kt + 1 < NKT) { G_LOAD(kt + 1); }
        __syncthreads();
        const float* pB = As + bb * ROWS * PSROW;
        const float* wB = Bs + bb * 32 * BST;
#pragma unroll
        for (int kk = 0; kk < 4; kk++) {
            const int k0 = kk * 8;
            uint32_t a[MT][4];
#pragma unroll
            for (int mt = 0; mt < MT; mt++) {
                const float* pr = pB + (wr * 16 * MT + mt * 16 + ar) * PSROW + k0 + ak;
                a[mt][0] = __float_as_uint(pr[0]);
                a[mt][1] = __float_as_uint(pr[8 * PSROW]);
                a[mt][2] = __float_as_uint(pr[4]);
                a[mt][3] = __float_as_uint(pr[8 * PSROW + 4]);
            }
#pragma unroll
            for (int nt = 0; nt < NT; nt++) {
                const int n = wc * (NT * 8) + nt * 8 + ar;
                uint32_t b0 = __float_as_uint(wB[(k0 + ak) * BST + n]);
                uint32_t b1 = __float_as_uint(wB[(k0 + ak + 4) * BST + n]);
#pragma unroll
                for (int mt = 0; mt < MT; mt++)
                    mma_tf32(d[mt][nt], a[mt], b0, b1);
            }
        }
    }
#undef G_LOAD
#undef G_STS
    __syncthreads();
    // ---- epilogue: packed fp16 store + fused src/dst (partial if CSPLIT>1) ----
#pragma unroll
    for (int mt = 0; mt < MT; mt++) {
        const int r0 = wr * 16 * MT + mt * 16 + ar;
        const int r1 = r0 + 8;
        const int R0 = i0 + r0, R1 = i0 + r1;
        const size_t pb0 = packed_base(R0), pb1 = packed_base(R1);
        float s10 = 0.f, s20 = 0.f, s11 = 0.f, s21 = 0.f;
#pragma unroll
        for (int nt = 0; nt < NT; nt++) {
            const int cl = wc * (NT * 8) + nt * 8 + 2 * ak;
            const int c  = coloff + cl;
            float t0 = d[mt][nt][0], t1 = d[mt][nt][1];
            float t2 = d[mt][nt][2], t3 = d[mt][nt][3];
            Cpb[pb0 + (size_t)c * 4]       = __float2half_rn(t0);
            Cpb[pb0 + (size_t)(c + 1) * 4] = __float2half_rn(t1);
            Cpb[pb1 + (size_t)c * 4]       = __float2half_rn(t2);
            Cpb[pb1 + (size_t)(c + 1) * 4] = __float2half_rn(t3);
            s10 += t0 * sa[c] + t1 * sa[c + 1];
            s20 += t0 * sa[FH + c] + t1 * sa[FH + c + 1];
            s11 += t2 * sa[c] + t3 * sa[c + 1];
            s21 += t2 * sa[FH + c] + t3 * sa[FH + c + 1];
        }
        s10 += __shfl_down_sync(0xffffffffu, s10, 2);
        s10 += __shfl_down_sync(0xffffffffu, s10, 1);
        s20 += __shfl_down_sync(0xffffffffu, s20, 2);
        s20 += __shfl_down_sync(0xffffffffu, s20, 1);
        s11 += __shfl_down_sync(0xffffffffu, s11, 2);
        s11 += __shfl_down_sync(0xffffffffu, s11, 1);
        s21 += __shfl_down_sync(0xffffffffu, s21, 2);
        s21 += __shfl_down_sync(0xffffffffu, s21, 1);
        if (ak == 0) {
            lsm[r0 * 8 + wc * 2]     = s10;
            lsm[r0 * 8 + wc * 2 + 1] = s20;
            lsm[r1 * 8 + wc * 2]     = s11;
            lsm[r1 * 8 + wc * 2 + 1] = s21;
        }
    }
    __syncthreads();
    if (tid < ROWS) {
        float s1 = lsm[tid*8] + lsm[tid*8+2] + lsm[tid*8+4] + lsm[tid*8+6];
        float s2 = lsm[tid*8+1] + lsm[tid*8+3] + lsm[tid*8+5] + lsm[tid*8+7];
        srcb[i0 + tid] = s1;
        dstb[i0 + tid] = s2;
    }
}

#define GEMM_SMEM(R, CS) (2 * (R) * PSROW * 4 + 2 * 32 * (256 / (CS) + 8) * 4 + \
                          512 * 4 + (R) * 8 * 4)

// ---------------- K1b: combine GEMM2 src/dst partials ------------------------
__global__ void srccomb_kernel() {
    const int i = blockIdx.x * blockDim.x + threadIdx.x;
    g_src2[i] = g_srcp[i] + g_srcp[NV + i];
    g_dst2[i] = g_dstp[i] + g_dstp[NV + i];
}

// ---------------- K3: fp16 mma fused attention, KT=64 per phase --------------
// (R11-proven structure) 128x256 tile, 512 threads, 16 warps (4x4),
// per-SMSP phase stagger, 64 neighbors/barrier, 3-buffer cp.async depth-2.
#define ATTN_SMEM (2 * 128 * PSTW * 4 + 3 * 16 * WBW * 4 + 512 * 4)

template <int NSPLIT>
__global__ void __launch_bounds__(512, 1)
attn_kernel() {
    extern __shared__ char smem[];
    float* Ps    = (float*)smem;                          // [2][128*PSTW]
    float* Whs   = (float*)(smem + 2 * 128 * PSTW * 4);   // [3][16*WBW]
    float* lpart = (float*)(smem + 2 * 128 * PSTW * 4 + 3 * 16 * WBW * 4);
    const uint32_t whs_s = (uint32_t)__cvta_generic_to_shared(Whs);

    const int tid = threadIdx.x;
    const int wid = tid >> 5, lane = tid & 31;
    const int wr = wid >> 2, wc = wid & 3;
    const int i0 = blockIdx.x * 128;
    const bool mmaFirst = ((wid >> 2) & 1) != 0;   // per-SMSP 2/2 split

    const __half* WhP; const float* srcT; const float* dR;
    int jbase, NKT;
    if (NSPLIT > 1) {
        WhP = g_Wh2P; srcT = g_src2; dR = g_dst2;
        jbase = blockIdx.y * (NV / NSPLIT);
        NKT = (NV / NSPLIT) / 64;
    } else {
        const int b = blockIdx.z;
        WhP = g_Wh1P + (size_t)b * NV * FH;
        srcT = g_src1 + b * NV; dR = g_dst1 + b * NV;
        jbase = 0; NKT = NV / 64;
    }

    const int prow = tid >> 2;          // 0..127
    const int q_   = tid & 3;
    const float si = srcT[i0 + prow];
    const unsigned* adjrow = g_adjbits + (size_t)(i0 + prow) * NW + (jbase >> 5);
    const int ar = lane >> 2, ak = lane & 3;

    // cp.async mapping: thread -> (group row tid>>5 of 16, chunk tid&31)
    const __half* wsrc0 = WhP + (size_t)(jbase >> 5) * 8192 +
                          (size_t)(tid >> 5) * 1024 + (size_t)(tid & 31) * 8;
    const uint32_t wdst0 = whs_s +
                           (uint32_t)((tid >> 5) * WBW + (tid & 31) * 4) * 4u;

    float d[2][8][4];
#pragma unroll
    for (int mt = 0; mt < 2; mt++)
#pragma unroll
        for (int nt = 0; nt < 8; nt++)
#pragma unroll
            for (int v = 0; v < 4; v++) d[mt][nt][v] = 0.f;
    float lsum = 0.f;

    const int kb_ = (q_ < 2) ? 4 * q_ : 4 * q_ + 8;   // 0,4,16,20
    const int s_  = prow & 7;

#define COMPUTE_P(kt_, pbuf_)                                                 \
    {                                                                         \
        uint2* pr_ = (uint2*)((pbuf_) + prow * PSTW);                         \
        _Pragma("unroll")                                                     \
        for (int h_ = 0; h_ < 2; h_++) {                                      \
            const int j0_ = jbase + (kt_) * 64 + 32 * h_;                     \
            const unsigned aw_ = adjrow[2 * (kt_) + h_];                      \
            float4 dv1 = *(const float4*)(dR + j0_ + kb_);                    \
            float4 dv2 = *(const float4*)(dR + j0_ + kb_ + 8);                \
            float dd_[8] = {dv1.x, dv1.y, dv1.z, dv1.w,                       \
                            dv2.x, dv2.y, dv2.z, dv2.w};                      \
            float p_[8];                                                      \
            _Pragma("unroll")                                                 \
            for (int u_ = 0; u_ < 8; u_++) {                                  \
                float e_ = si + dd_[u_];                                      \
                e_ = fmaxf(e_, 0.2f * e_);                                    \
                float pp_ = __expf(e_);                                       \
                pp_ = fminf(pp_, 65000.f);                                    \
                const int bit_ = kb_ + ((u_ < 4) ? u_ : u_ + 4);              \
                pp_ = ((aw_ >> bit_) & 1u) ? pp_ : 0.f;                       \
                lsum += pp_;                                                  \
                p_[u_] = pp_;                                                 \
            }                                                                 \
            const int g0_ = 2 * q_;                                           \
            pr_[8 * h_ + (g0_ ^ s_)] =                                        \
                make_uint2(f2h2(p_[0], p_[1]), f2h2(p_[4], p_[5]));           \
            pr_[8 * h_ + ((g0_ + 1) ^ s_)] =                                  \
                make_uint2(f2h2(p_[2], p_[3]), f2h2(p_[6], p_[7]));           \
        }                                                                     \
    }

#define ISSUE_WH(kt_, buf_)                                                   \
    {                                                                         \
        const __half* wp_ = wsrc0 + (size_t)(kt_) * 16384;                    \
        const uint32_t wd_ = wdst0 + (uint32_t)(buf_) * (16u * WBW * 4u);     \
        _Pragma("unroll")                                                     \
        for (int q2_ = 0; q2_ < 4; q2_++)                                     \
            cp16(wd_ + q2_ * 512u, wp_ + q2_ * 256);                          \
    }

#define PREP_STEP(kt_)                                                        \
    {                                                                         \
        if ((kt_) + 2 < NKT) { ISSUE_WH((kt_) + 2, ((kt_) + 2) % 3); }        \
        cp_commit();                                                          \
        if ((kt_) + 1 < NKT) {                                                \
            COMPUTE_P((kt_) + 1, Ps + (((kt_) + 1) & 1) * 128 * PSTW);        \
        }                                                                     \
    }

#define MMA_STEP(kt_)                                                         \
    {                                                                         \
        const float* pB = Ps + ((kt_) & 1) * 128 * PSTW;                      \
        const float* wB = Whs + ((kt_) % 3) * 16 * WBW;                       \
        _Pragma("unroll")                                                     \
        for (int kk = 0; kk < 4; kk++) {                                      \
            const int gi_ = kk * 4 + ak;                                      \
            const int idx_ = (gi_ & 8) | ((gi_ & 7) ^ ar);                    \
            uint32_t a[2][4];                                                 \
            _Pragma("unroll")                                                 \
            for (int mt = 0; mt < 2; mt++) {                                  \
                const int row_ = wr * 32 + mt * 16 + ar;                      \
                uint2 u_ = ((const uint2*)(pB + row_ * PSTW))[idx_];          \
                uint2 v_ = ((const uint2*)(pB + (row_ + 8) * PSTW))[idx_];    \
                a[mt][0] = u_.x; a[mt][1] = v_.x;                             \
                a[mt][2] = u_.y; a[mt][3] = v_.y;                             \
            }                                                                 \
            _Pragma("unroll")                                                 \
            for (int nt = 0; nt < 8; nt++) {                                  \
                const int n = wc * 64 + nt * 8 + ar;                          \
                uint2 b_ = ((const uint2*)(wB + gi_ * WBW))[n];               \
                _Pragma("unroll")                                             \
                for (int mt = 0; mt < 2; mt++)                                \
                    mma_f16(d[mt][nt], a[mt], b_.x, b_.y);                    \
            }                                                                 \
        }                                                                     \
    }

    // ---- prologue ----
    ISSUE_WH(0, 0); cp_commit();
    if (1 < NKT) { ISSUE_WH(1, 1); }
    cp_commit();
    COMPUTE_P(0, Ps);

    for (int kt = 0; kt < NKT; kt++) {
        cp_wait1();          // Wh(kt) complete (per-thread)
        __syncthreads();     // visibility; prev MMA reads done
        if (mmaFirst) {
            MMA_STEP(kt);
            PREP_STEP(kt);
        } else {
            PREP_STEP(kt);
            MMA_STEP(kt);
        }
    }
    __syncthreads();
    lpart[tid] = lsum;       // lpart[prow*4 + q]
    __syncthreads();

    if (NSPLIT > 1) {
        float* np = g_np + (size_t)blockIdx.y * NV * FO;
#pragma unroll
        for (int mt = 0; mt < 2; mt++) {
            const int r0 = wr * 32 + mt * 16 + ar;
            const int r1 = r0 + 8;
#pragma unroll
            for (int nt = 0; nt < 8; nt++) {
                const int c = wc * 64 + nt * 8 + 2 * ak;
                *(float2*)(np + (size_t)(i0 + r0) * FO + c) = make_float2(d[mt][nt][0], d[mt][nt][1]);
                *(float2*)(np + (size_t)(i0 + r1) * FO + c) = make_float2(d[mt][nt][2], d[mt][nt][3]);
            }
        }
        if (tid < 128) {
            float l = lpart[tid * 4] + lpart[tid * 4 + 1] +
                      lpart[tid * 4 + 2] + lpart[tid * 4 + 3];
            g_lp[blockIdx.y * NV + i0 + tid] = l;
        }
    } else {
        float* out = g_h1;
        const int coloff = blockIdx.z * FH;
#pragma unroll
        for (int mt = 0; mt < 2; mt++) {
            const int r0 = wr * 32 + mt * 16 + ar;
            const int r1 = r0 + 8;
            const float l0 = lpart[r0*4] + lpart[r0*4+1] + lpart[r0*4+2] + lpart[r0*4+3];
            const float l1 = lpart[r1*4] + lpart[r1*4+1] + lpart[r1*4+2] + lpart[r1*4+3];
            const float rl0 = 1.0f / l0, rl1 = 1.0f / l1;
#pragma unroll
            for (int nt = 0; nt < 8; nt++) {
                const int c = coloff + wc * 64 + nt * 8 + 2 * ak;
                float o0 = d[mt][nt][0] * rl0, o1 = d[mt][nt][1] * rl0;
                float o2 = d[mt][nt][2] * rl1, o3 = d[mt][nt][3] * rl1;
                o0 = o0 > 0.f ? o0 : (__expf(o0) - 1.0f);
                o1 = o1 > 0.f ? o1 : (__expf(o1) - 1.0f);
                o2 = o2 > 0.f ? o2 : (__expf(o2) - 1.0f);
                o3 = o3 > 0.f ? o3 : (__expf(o3) - 1.0f);
                *(float2*)(out + (size_t)(i0 + r0) * F2 + c) = make_float2(o0, o1);
                *(float2*)(out + (size_t)(i0 + r1) * F2 + c) = make_float2(o2, o3);
            }
        }
    }
#undef COMPUTE_P
#undef ISSUE_WH
#undef PREP_STEP
#undef MMA_STEP
}

// ---------------- K4: combine 4 split partials (layer 1 epilogue) ------------
__global__ void combine_kernel(float* __restrict__ out) {
    const int i = blockIdx.x;
    const int c = threadIdx.x;
    float l = 0.f, n = 0.f;
#pragma unroll
    for (int s = 0; s < 4; s++) {
        l += g_lp[s * NV + i];
        n += g_np[(size_t)s * NV * FO + (size_t)i * FO + c];
    }
    out[(size_t)i * FO + c] = n / l;
}

// ---------------- launch -----------------------------------------------------
extern "C" void kernel_launch(void* const* d_in, const int* in_sizes, int n_in,
                              void* d_out, int out_size) {
    (void)in_sizes; (void)n_in; (void)out_size;
    const float* x   = (const float*)d_in[0];
    const int*   adj = (const int*)d_in[1];
    const float* W1  = (const float*)d_in[2];
    const float* a1  = (const float*)d_in[3];
    const float* W2  = (const float*)d_in[4];
    const float* a2  = (const float*)d_in[5];
    float* out = (float*)d_out;

    static int inited = 0;
    if (!inited) {
        cudaFuncSetAttribute(gemm_tf32_kernel<128, 1>,
            cudaFuncAttributeMaxDynamicSharedMemorySize, GEMM_SMEM(128, 1));
        cudaFuncSetAttribute(gemm_tf32_kernel<64, 2>,
            cudaFuncAttributeMaxDynamicSharedMemorySize, GEMM_SMEM(64, 2));
        cudaFuncSetAttribute(attn_kernel<1>,
            cudaFuncAttributeMaxDynamicSharedMemorySize, ATTN_SMEM);
        cudaFuncSetAttribute(attn_kernel<4>,
            cudaFuncAttributeMaxDynamicSharedMemorySize, ATTN_SMEM);
        inited = 1;
    }

    __half* Wh1pp; cudaGetSymbolAddress((void**)&Wh1pp, g_Wh1P);
    __half* Wh2pp; cudaGetSymbolAddress((void**)&Wh2pp, g_Wh2P);
    float*  h1p;   cudaGetSymbolAddress((void**)&h1p,   g_h1);
    float*  src1p; cudaGetSymbolAddress((void**)&src1p, g_src1);
    float*  dst1p; cudaGetSymbolAddress((void**)&dst1p, g_dst1);
    float*  srcpp; cudaGetSymbolAddress((void**)&srcpp, g_srcp);
    float*  dstpp; cudaGetSymbolAddress((void**)&dstpp, g_dstp);

    adjbits_kernel<<<(NV * NV) / 256, 256>>>(adj);
    gemm_tf32_kernel<128, 1><<<dim3(NV / 128, NHEADS), 512, GEMM_SMEM(128, 1)>>>(
        x, W1, Wh1pp, a1, src1p, dst1p, F1, (long)F1 * FH, (long)NV * FH);
    attn_kernel<1><<<dim3(NV / 128, 1, NHEADS), 512, ATTN_SMEM>>>();
    gemm_tf32_kernel<64, 2><<<dim3(NV / 64, 2), 512, GEMM_SMEM(64, 2)>>>(
        h1p, W2, Wh2pp, a2, srcpp, dstpp, F2, 0L, 0L);
    srccomb_kernel<<<NV / 256, 256>>>();
    attn_kernel<4><<<dim3(NV / 128, 4), 512, ATTN_SMEM>>>();
    combine_kernel<<<NV, 256>>>(out);
}

// round 16
// speedup vs baseline: 1.3704x; 1.0786x over previous
#include <cuda_runtime.h>
#include <cuda_fp16.h>
#include <cstdint>

#define NV 4096
#define F1 512
#define FH 256
#define NHEADS 4
#define F2 1024   // nhid * nheads
#define FO 256
#define NW (NV/32) // 128 bitmask words per row

#define PSROW 36   // gemm A tile row stride (words)
#define PSTW  40   // attn P tile row stride (words; 32 used), swizzled groups
#define WBW   520  // attn Wh buf row stride (words; 512 used): 520%32==8

// ---------------- scratch (static device memory; no allocations) ------------
__device__ __align__(16) __half g_Wh1P[NHEADS * NV * FH];  // packed fp16 B-frag layout
__device__ __align__(16) float  g_h1[NV * F2];             // tf32-rounded at write
__device__ __align__(16) __half g_Wh2P[NV * FO];
__device__ __align__(16) float  g_xr[NV * F1];             // tf32-rounded x
__device__ __align__(16) float  g_W1r[NHEADS * F1 * FH];   // tf32-rounded W1
__device__ __align__(16) float  g_W2r[F2 * FO];            // tf32-rounded W2
__device__ __align__(16) float  g_src1[NHEADS * NV];
__device__ __align__(16) float  g_dst1[NHEADS * NV];
__device__ __align__(16) float  g_src2[NV];
__device__ __align__(16) float  g_dst2[NV];
__device__ __align__(16) float  g_srcp[2 * NV];          // GEMM2 col-split partials
__device__ __align__(16) float  g_dstp[2 * NV];
__device__ __align__(16) float  g_np[4 * NV * FO];       // L1 split numerators
__device__ __align__(16) float  g_lp[4 * NV];            // L1 split denominators
__device__ __align__(16) unsigned g_adjbits[NV * NW];    // 2 MB

// ---------------- helpers -----------------------------------------------------
__device__ __forceinline__ float tf32r(float x) {
    uint32_t u;
    asm("cvt.rna.tf32.f32 %0, %1;" : "=r"(u) : "f"(x));
    return __uint_as_float(u);
}
__device__ __forceinline__ float4 tf32r4(float4 v) {
    return make_float4(tf32r(v.x), tf32r(v.y), tf32r(v.z), tf32r(v.w));
}
__device__ __forceinline__ uint32_t f2h2(float a, float b) {
    __half2 h = __floats2half2_rn(a, b);
    return *reinterpret_cast<uint32_t*>(&h);
}
__device__ __forceinline__ void mma_tf32(float* d, const uint32_t* a,
                                         uint32_t b0, uint32_t b1) {
    asm volatile(
        "mma.sync.aligned.m16n8k8.row.col.f32.tf32.tf32.f32 "
        "{%0,%1,%2,%3}, {%4,%5,%6,%7}, {%8,%9}, {%0,%1,%2,%3};"
        : "+f"(d[0]), "+f"(d[1]), "+f"(d[2]), "+f"(d[3])
        : "r"(a[0]), "r"(a[1]), "r"(a[2]), "r"(a[3]), "r"(b0), "r"(b1));
}
__device__ __forceinline__ void mma_f16(float* d, const uint32_t* a,
                                        uint32_t b0, uint32_t b1) {
    asm volatile(
        "mma.sync.aligned.m16n8k16.row.col.f32.f16.f16.f32 "
        "{%0,%1,%2,%3}, {%4,%5,%6,%7}, {%8,%9}, {%0,%1,%2,%3};"
        : "+f"(d[0]), "+f"(d[1]), "+f"(d[2]), "+f"(d[3])
        : "r"(a[0]), "r"(a[1]), "r"(a[2]), "r"(a[3]), "r"(b0), "r"(b1));
}
__device__ __forceinline__ void cp16(uint32_t saddr, const void* gptr) {
    asm volatile("cp.async.cg.shared.global [%0], [%1], 16;"
                 :: "r"(saddr), "l"(gptr));
}
__device__ __forceinline__ void cp_commit() {
    asm volatile("cp.async.commit_group;");
}
__device__ __forceinline__ void cp_wait1() {
    asm volatile("cp.async.wait_group 1;");
}
// packed fp16 layout: per 32-node block, 8 group-rows of 256*(4 halves);
// node jl -> group g = (jl>>4)*4 + ((jl&7)>>1), slot = (jl&1) + ((jl>>3)&1)*2
__device__ __forceinline__ size_t packed_base(int R) {
    int blk = R >> 5, jl = R & 31;
    int g = (jl >> 4) * 4 + ((jl & 7) >> 1);
    int slot = (jl & 1) + ((jl >> 3) & 1) * 2;
    return (size_t)blk * 8192 + (size_t)g * 1024 + slot;
}

// ---------------- K-pre: RNA-round fp32 array to tf32 ------------------------
__global__ void roundcpy_kernel(const float* __restrict__ in,
                                float* __restrict__ out) {
    const int i = (blockIdx.x * blockDim.x + threadIdx.x) * 4;
    *(float4*)(out + i) = tf32r4(*(const float4*)(in + i));
}

// ---------------- K0: adjacency -> bitmask (MLP=4) ----------------------------
__global__ void adjbits_kernel(const int* __restrict__ adj) {
    const int base = blockIdx.x * 1024 + threadIdx.x;
#pragma unroll
    for (int k = 0; k < 4; k++) {
        const int idx = base + k * 256;
        unsigned bit = (adj[idx] != 0) ? 1u : 0u;
        unsigned w = __ballot_sync(0xffffffffu, bit);
        if ((threadIdx.x & 31) == 0) g_adjbits[idx >> 5] = w;
    }
}

// ---------------- K1: tf32 mma GEMM + fused src/dst, cp.async pipeline -------
// Inputs are pre-rounded tf32 -> HW truncation in MMA is exact (== RNA).
// CSPLIT=1: blockIdx.y = head. CSPLIT=2: blockIdx.y = column half (GEMM2),
// src/dst written as per-half partials (combined by srccomb_kernel).
template <int ROWS, int CSPLIT>
__global__ void __launch_bounds__(512, 1)
gemm_tf32_kernel(const float* __restrict__ A, const float* __restrict__ B,
                 __half* __restrict__ Cp, const float* __restrict__ avec,
                 float* __restrict__ src, float* __restrict__ dst,
                 int K, long bStride, long cStride) {
    constexpr int MT  = ROWS / 64;
    constexpr int TPR = 512 / ROWS;       // threads per A-row (4 or 8)
    constexpr int AK  = 32 / TPR;         // A cols per thread (8 or 4)
    constexpr int NCOLS = 256 / CSPLIT;   // output cols per CTA
    constexpr int NT  = NCOLS / 32;       // n-tiles per warp (8 or 4)
    constexpr int BST = NCOLS + 8;        // B tile stride: =8 (mod 32)
    constexpr int BQ  = NCOLS / 64;       // B float4 chunks per thread
    extern __shared__ char smem[];
    float* As  = (float*)smem;                            // [3][ROWS*PSROW]
    float* Bs  = (float*)(smem + 3 * ROWS * PSROW * 4);   // [3][32*BST]
    float* sa  = (float*)(smem + 3 * ROWS * PSROW * 4 + 3 * 32 * BST * 4);
    float* lsm = sa + 2 * FH;                             // [ROWS][8]
    const uint32_t as_s = (uint32_t)__cvta_generic_to_shared(As);
    const uint32_t bs_s = (uint32_t)__cvta_generic_to_shared(Bs);

    const int tid = threadIdx.x;
    const int wid = tid >> 5, lane = tid & 31;
    const int wr = wid >> 2, wc = wid & 3;
    const int b  = (CSPLIT > 1) ? 0 : blockIdx.y;
    const int cs = (CSPLIT > 1) ? blockIdx.y : 0;
    const int coloff = cs * NCOLS;
    const float* Bb = B + (size_t)b * bStride;
    __half* Cpb = Cp + (size_t)b * cStride;
    const float* av = avec + (size_t)b * 2 * FH;
    float* srcb = src + (size_t)((CSPLIT > 1) ? cs : b) * NV;
    float* dstb = dst + (size_t)((CSPLIT > 1) ? cs : b) * NV;
    const int i0 = blockIdx.x * ROWS;

    sa[tid] = av[tid];   // 512 threads load 2*FH floats

    const int arow = tid / TPR, ak0 = (tid % TPR) * AK;
    const int jrow = tid >> 4, fbase = (tid & 15) * 4;
    const int ar = lane >> 2, ak = lane & 3;

    float d[MT][NT][4];
#pragma unroll
    for (int mt = 0; mt < MT; mt++)
#pragma unroll
        for (int nt = 0; nt < NT; nt++)
#pragma unroll
            for (int v = 0; v < 4; v++) d[mt][nt][v] = 0.f;

    const int NKT = K / 32;

#define G_ISSUE(kt_, buf_)                                                    \
    {                                                                         \
        const float* bp_ = Bb + (size_t)((kt_) * 32 + jrow) * FH + coloff + fbase; \
        const uint32_t bd_ = bs_s +                                           \
            (uint32_t)((buf_) * 32 * BST + jrow * BST + fbase) * 4u;          \
        _Pragma("unroll")                                                     \
        for (int q_ = 0; q_ < BQ; q_++)                                       \
            cp16(bd_ + q_ * 64u * 4u, bp_ + 64 * q_);                         \
        const float* ap_ = A + (size_t)(i0 + arow) * K + (kt_) * 32 + ak0;    \
        const uint32_t ad_ = as_s +                                           \
            (uint32_t)((buf_) * ROWS * PSROW + arow * PSROW + ak0) * 4u;      \
        _Pragma("unroll")                                                     \
        for (int q_ = 0; q_ < AK / 4; q_++)                                   \
            cp16(ad_ + q_ * 16u, ap_ + q_ * 4);                               \
    }

    G_ISSUE(0, 0); cp_commit();
    G_ISSUE(1, 1); cp_commit();

    for (int kt = 0; kt < NKT; kt++) {
        cp_wait1();
        __syncthreads();
        if (kt + 2 < NKT) { G_ISSUE(kt + 2, (kt + 2) % 3); }
        cp_commit();
        const float* pB = As + (kt % 3) * ROWS * PSROW;
        const float* wB = Bs + (kt % 3) * 32 * BST;
#pragma unroll
        for (int kk = 0; kk < 4; kk++) {
            const int k0 = kk * 8;
            uint32_t a[MT][4];
#pragma unroll
            for (int mt = 0; mt < MT; mt++) {
                const float* pr = pB + (wr * 16 * MT + mt * 16 + ar) * PSROW + k0 + ak;
                a[mt][0] = __float_as_uint(pr[0]);
                a[mt][1] = __float_as_uint(pr[8 * PSROW]);
                a[mt][2] = __float_as_uint(pr[4]);
                a[mt][3] = __float_as_uint(pr[8 * PSROW + 4]);
            }
#pragma unroll
            for (int nt = 0; nt < NT; nt++) {
                const int n = wc * (NT * 8) + nt * 8 + ar;
                uint32_t b0 = __float_as_uint(wB[(k0 + ak) * BST + n]);
                uint32_t b1 = __float_as_uint(wB[(k0 + ak + 4) * BST + n]);
#pragma unroll
                for (int mt = 0; mt < MT; mt++)
                    mma_tf32(d[mt][nt], a[mt], b0, b1);
            }
        }
    }
#undef G_ISSUE
    __syncthreads();
    // ---- epilogue: packed fp16 store + fused src/dst (partial if CSPLIT>1) ----
#pragma unroll
    for (int mt = 0; mt < MT; mt++) {
        const int r0 = wr * 16 * MT + mt * 16 + ar;
        const int r1 = r0 + 8;
        const int R0 = i0 + r0, R1 = i0 + r1;
        const size_t pb0 = packed_base(R0), pb1 = packed_base(R1);
        float s10 = 0.f, s20 = 0.f, s11 = 0.f, s21 = 0.f;
#pragma unroll
        for (int nt = 0; nt < NT; nt++) {
            const int cl = wc * (NT * 8) + nt * 8 + 2 * ak;
            const int c  = coloff + cl;
            float t0 = d[mt][nt][0], t1 = d[mt][nt][1];
            float t2 = d[mt][nt][2], t3 = d[mt][nt][3];
            Cpb[pb0 + (size_t)c * 4]       = __float2half_rn(t0);
            Cpb[pb0 + (size_t)(c + 1) * 4] = __float2half_rn(t1);
            Cpb[pb1 + (size_t)c * 4]       = __float2half_rn(t2);
            Cpb[pb1 + (size_t)(c + 1) * 4] = __float2half_rn(t3);
            s10 += t0 * sa[c] + t1 * sa[c + 1];
            s20 += t0 * sa[FH + c] + t1 * sa[FH + c + 1];
            s11 += t2 * sa[c] + t3 * sa[c + 1];
            s21 += t2 * sa[FH + c] + t3 * sa[FH + c + 1];
        }
        s10 += __shfl_down_sync(0xffffffffu, s10, 2);
        s10 += __shfl_down_sync(0xffffffffu, s10, 1);
        s20 += __shfl_down_sync(0xffffffffu, s20, 2);
        s20 += __shfl_down_sync(0xffffffffu, s20, 1);
        s11 += __shfl_down_sync(0xffffffffu, s11, 2);
        s11 += __shfl_down_sync(0xffffffffu, s11, 1);
        s21 += __shfl_down_sync(0xffffffffu, s21, 2);
        s21 += __shfl_down_sync(0xffffffffu, s21, 1);
        if (ak == 0) {
            lsm[r0 * 8 + wc * 2]     = s10;
            lsm[r0 * 8 + wc * 2 + 1] = s20;
            lsm[r1 * 8 + wc * 2]     = s11;
            lsm[r1 * 8 + wc * 2 + 1] = s21;
        }
    }
    __syncthreads();
    if (tid < ROWS) {
        float s1 = lsm[tid*8] + lsm[tid*8+2] + lsm[tid*8+4] + lsm[tid*8+6];
        float s2 = lsm[tid*8+1] + lsm[tid*8+3] + lsm[tid*8+5] + lsm[tid*8+7];
        srcb[i0 + tid] = s1;
        dstb[i0 + tid] = s2;
    }
}

#define GEMM_SMEM(R, CS) (3 * (R) * PSROW * 4 + 3 * 32 * (256 / (CS) + 8) * 4 + \
                          512 * 4 + (R) * 8 * 4)

// ---------------- K1b: combine GEMM2 src/dst partials ------------------------
__global__ void srccomb_kernel() {
    const int i = blockIdx.x * blockDim.x + threadIdx.x;
    g_src2[i] = g_srcp[i] + g_srcp[NV + i];
    g_dst2[i] = g_dstp[i] + g_dstp[NV + i];
}

// ---------------- K3: fp16 mma fused attention, KT=64 per phase --------------
// (R11-proven structure) 128x256 tile, 512 threads, 16 warps (4x4),
// per-SMSP phase stagger, 64 neighbors/barrier, 3-buffer cp.async depth-2.
// L0 writes g_h1 tf32-rounded (consumed raw by gemm2's cp.async path).
#define ATTN_SMEM (2 * 128 * PSTW * 4 + 3 * 16 * WBW * 4 + 512 * 4)

template <int NSPLIT>
__global__ void __launch_bounds__(512, 1)
attn_kernel() {
    extern __shared__ char smem[];
    float* Ps    = (float*)smem;                          // [2][128*PSTW]
    float* Whs   = (float*)(smem + 2 * 128 * PSTW * 4);   // [3][16*WBW]
    float* lpart = (float*)(smem + 2 * 128 * PSTW * 4 + 3 * 16 * WBW * 4);
    const uint32_t whs_s = (uint32_t)__cvta_generic_to_shared(Whs);

    const int tid = threadIdx.x;
    const int wid = tid >> 5, lane = tid & 31;
    const int wr = wid >> 2, wc = wid & 3;
    const int i0 = blockIdx.x * 128;
    const bool mmaFirst = ((wid >> 2) & 1) != 0;   // per-SMSP 2/2 split

    const __half* WhP; const float* srcT; const float* dR;
    int jbase, NKT;
    if (NSPLIT > 1) {
        WhP = g_Wh2P; srcT = g_src2; dR = g_dst2;
        jbase = blockIdx.y * (NV / NSPLIT);
        NKT = (NV / NSPLIT) / 64;
    } else {
        const int b = blockIdx.z;
        WhP = g_Wh1P + (size_t)b * NV * FH;
        srcT = g_src1 + b * NV; dR = g_dst1 + b * NV;
        jbase = 0; NKT = NV / 64;
    }

    const int prow = tid >> 2;          // 0..127
    const int q_   = tid & 3;
    const float si = srcT[i0 + prow];
    const unsigned* adjrow = g_adjbits + (size_t)(i0 + prow) * NW + (jbase >> 5);
    const int ar = lane >> 2, ak = lane & 3;

    // cp.async mapping: thread -> (group row tid>>5 of 16, chunk tid&31)
    const __half* wsrc0 = WhP + (size_t)(jbase >> 5) * 8192 +
                          (size_t)(tid >> 5) * 1024 + (size_t)(tid & 31) * 8;
    const uint32_t wdst0 = whs_s +
                           (uint32_t)((tid >> 5) * WBW + (tid & 31) * 4) * 4u;

    float d[2][8][4];
#pragma unroll
    for (int mt = 0; mt < 2; mt++)
#pragma unroll
        for (int nt = 0; nt < 8; nt++)
#pragma unroll
            for (int v = 0; v < 4; v++) d[mt][nt][v] = 0.f;
    float lsum = 0.f;

    const int kb_ = (q_ < 2) ? 4 * q_ : 4 * q_ + 8;   // 0,4,16,20
    const int s_  = prow & 7;

#define COMPUTE_P(kt_, pbuf_)                                                 \
    {                                                                         \
        uint2* pr_ = (uint2*)((pbuf_) + prow * PSTW);                         \
        _Pragma("unroll")                                                     \
        for (int h_ = 0; h_ < 2; h_++) {                                      \
            const int j0_ = jbase + (kt_) * 64 + 32 * h_;                     \
            const unsigned aw_ = adjrow[2 * (kt_) + h_];                      \
            float4 dv1 = *(const float4*)(dR + j0_ + kb_);                    \
            float4 dv2 = *(const float4*)(dR + j0_ + kb_ + 8);                \
            float dd_[8] = {dv1.x, dv1.y, dv1.z, dv1.w,                       \
                            dv2.x, dv2.y, dv2.z, dv2.w};                      \
            float p_[8];                                                      \
            _Pragma("unroll")                                                 \
            for (int u_ = 0; u_ < 8; u_++) {                                  \
                float e_ = si + dd_[u_];                                      \
                e_ = fmaxf(e_, 0.2f * e_);                                    \
                float pp_ = __expf(e_);                                       \
                pp_ = fminf(pp_, 65000.f);                                    \
                const int bit_ = kb_ + ((u_ < 4) ? u_ : u_ + 4);              \
                pp_ = ((aw_ >> bit_) & 1u) ? pp_ : 0.f;                       \
                lsum += pp_;                                                  \
                p_[u_] = pp_;                                                 \
            }                                                                 \
            const int g0_ = 2 * q_;                                           \
            pr_[8 * h_ + (g0_ ^ s_)] =                                        \
                make_uint2(f2h2(p_[0], p_[1]), f2h2(p_[4], p_[5]));           \
            pr_[8 * h_ + ((g0_ + 1) ^ s_)] =                                  \
                make_uint2(f2h2(p_[2], p_[3]), f2h2(p_[6], p_[7]));           \
        }                                                                     \
    }

#define ISSUE_WH(kt_, buf_)                                                   \
    {                                                                         \
        const __half* wp_ = wsrc0 + (size_t)(kt_) * 16384;                    \
        const uint32_t wd_ = wdst0 + (uint32_t)(buf_) * (16u * WBW * 4u);     \
        _Pragma("unroll")                                                     \
        for (int q2_ = 0; q2_ < 4; q2_++)                                     \
            cp16(wd_ + q2_ * 512u, wp_ + q2_ * 256);                          \
    }

#define PREP_STEP(kt_)                                                        \
    {                                                                         \
        if ((kt_) + 2 < NKT) { ISSUE_WH((kt_) + 2, ((kt_) + 2) % 3); }        \
        cp_commit();                                                          \
        if ((kt_) + 1 < NKT) {                                                \
            COMPUTE_P((kt_) + 1, Ps + (((kt_) + 1) & 1) * 128 * PSTW);        \
        }                                                                     \
    }

#define MMA_STEP(kt_)                                                         \
    {                                                                         \
        const float* pB = Ps + ((kt_) & 1) * 128 * PSTW;                      \
        const float* wB = Whs + ((kt_) % 3) * 16 * WBW;                       \
        _Pragma("unroll")                                                     \
        for (int kk = 0; kk < 4; kk++) {                                      \
            const int gi_ = kk * 4 + ak;                                      \
            const int idx_ = (gi_ & 8) | ((gi_ & 7) ^ ar);                    \
            uint32_t a[2][4];                                                 \
            _Pragma("unroll")                                                 \
            for (int mt = 0; mt < 2; mt++) {                                  \
                const int row_ = wr * 32 + mt * 16 + ar;                      \
                uint2 u_ = ((const uint2*)(pB + row_ * PSTW))[idx_];          \
                uint2 v_ = ((const uint2*)(pB + (row_ + 8) * PSTW))[idx_];    \
                a[mt][0] = u_.x; a[mt][1] = v_.x;                             \
                a[mt][2] = u_.y; a[mt][3] = v_.y;                             \
            }                                                                 \
            _Pragma("unroll")                                                 \
            for (int nt = 0; nt < 8; nt++) {                                  \
                const int n = wc * 64 + nt * 8 + ar;                          \
                uint2 b_ = ((const uint2*)(wB + gi_ * WBW))[n];               \
                _Pragma("unroll")                                             \
                for (int mt = 0; mt < 2; mt++)                                \
                    mma_f16(d[mt][nt], a[mt], b_.x, b_.y);                    \
            }                                                                 \
        }                                                                     \
    }

    // ---- prologue ----
    ISSUE_WH(0, 0); cp_commit();
    if (1 < NKT) { ISSUE_WH(1, 1); }
    cp_commit();
    COMPUTE_P(0, Ps);

    for (int kt = 0; kt < NKT; kt++) {
        cp_wait1();          // Wh(kt) complete (per-thread)
        __syncthreads();     // visibility; prev MMA reads done
        if (mmaFirst) {
            MMA_STEP(kt);
            PREP_STEP(kt);
        } else {
            PREP_STEP(kt);
            MMA_STEP(kt);
        }
    }
    __syncthreads();
    lpart[tid] = lsum;       // lpart[prow*4 + q]
    __syncthreads();

    if (NSPLIT > 1) {
        float* np = g_np + (size_t)blockIdx.y * NV * FO;
#pragma unroll
        for (int mt = 0; mt < 2; mt++) {
            const int r0 = wr * 32 + mt * 16 + ar;
            const int r1 = r0 + 8;
#pragma unroll
            for (int nt = 0; nt < 8; nt++) {
                const int c = wc * 64 + nt * 8 + 2 * ak;
                *(float2*)(np + (size_t)(i0 + r0) * FO + c) = make_float2(d[mt][nt][0], d[mt][nt][1]);
                *(float2*)(np + (size_t)(i0 + r1) * FO + c) = make_float2(d[mt][nt][2], d[mt][nt][3]);
            }
        }
        if (tid < 128) {
            float l = lpart[tid * 4] + lpart[tid * 4 + 1] +
                      lpart[tid * 4 + 2] + lpart[tid * 4 + 3];
            g_lp[blockIdx.y * NV + i0 + tid] = l;
        }
    } else {
        float* out = g_h1;
        const int coloff = blockIdx.z * FH;
#pragma unroll
        for (int mt = 0; mt < 2; mt++) {
            const int r0 = wr * 32 + mt * 16 + ar;
            const int r1 = r0 + 8;
            const float l0 = lpart[r0*4] + lpart[r0*4+1] + lpart[r0*4+2] + lpart[r0*4+3];
            const float l1 = lpart[r1*4] + lpart[r1*4+1] + lpart[r1*4+2] + lpart[r1*4+3];
            const float rl0 = 1.0f / l0, rl1 = 1.0f / l1;
#pragma unroll
            for (int nt = 0; nt < 8; nt++) {
                const int c = coloff + wc * 64 + nt * 8 + 2 * ak;
                float o0 = d[mt][nt][0] * rl0, o1 = d[mt][nt][1] * rl0;
                float o2 = d[mt][nt][2] * rl1, o3 = d[mt][nt][3] * rl1;
                o0 = o0 > 0.f ? o0 : (__expf(o0) - 1.0f);
                o1 = o1 > 0.f ? o1 : (__expf(o1) - 1.0f);
                o2 = o2 > 0.f ? o2 : (__expf(o2) - 1.0f);
                o3 = o3 > 0.f ? o3 : (__expf(o3) - 1.0f);
                *(float2*)(out + (size_t)(i0 + r0) * F2 + c) =
                    make_float2(tf32r(o0), tf32r(o1));
                *(float2*)(out + (size_t)(i0 + r1) * F2 + c) =
                    make_float2(tf32r(o2), tf32r(o3));
            }
        }
    }
#undef COMPUTE_P
#undef ISSUE_WH
#undef PREP_STEP
#undef MMA_STEP
}

// ---------------- K4: combine 4 split partials (layer 1 epilogue) ------------
__global__ void combine_kernel(float* __restrict__ out) {
    const int i = blockIdx.x;
    const int c = threadIdx.x;
    float l = 0.f, n = 0.f;
#pragma unroll
    for (int s = 0; s < 4; s++) {
        l += g_lp[s * NV + i];
        n += g_np[(size_t)s * NV * FO + (size_t)i * FO + c];
    }
    out[(size_t)i * FO + c] = n / l;
}

// ---------------- launch -----------------------------------------------------
extern "C" void kernel_launch(void* const* d_in, const int* in_sizes, int n_in,
                              void* d_out, int out_size) {
    (void)in_sizes; (void)n_in; (void)out_size;
    const float* x   = (const float*)d_in[0];
    const int*   adj = (const int*)d_in[1];
    const float* W1  = (const float*)d_in[2];
    const float* a1  = (const float*)d_in[3];
    const float* W2  = (const float*)d_in[4];
    const float* a2  = (const float*)d_in[5];
    float* out = (float*)d_out;

    static int inited = 0;
    if (!inited) {
        cudaFuncSetAttribute(gemm_tf32_kernel<128, 1>,
            cudaFuncAttributeMaxDynamicSharedMemorySize, GEMM_SMEM(128, 1));
        cudaFuncSetAttribute(gemm_tf32_kernel<64, 2>,
            cudaFuncAttributeMaxDynamicSharedMemorySize, GEMM_SMEM(64, 2));
        cudaFuncSetAttribute(attn_kernel<1>,
            cudaFuncAttributeMaxDynamicSharedMemorySize, ATTN_SMEM);
        cudaFuncSetAttribute(attn_kernel<4>,
            cudaFuncAttributeMaxDynamicSharedMemorySize, ATTN_SMEM);
        inited = 1;
    }

    __half* Wh1pp; cudaGetSymbolAddress((void**)&Wh1pp, g_Wh1P);
    __half* Wh2pp; cudaGetSymbolAddress((void**)&Wh2pp, g_Wh2P);
    float*  h1p;   cudaGetSymbolAddress((void**)&h1p,   g_h1);
    float*  xrp;   cudaGetSymbolAddress((void**)&xrp,   g_xr);
    float*  w1rp;  cudaGetSymbolAddress((void**)&w1rp,  g_W1r);
    float*  w2rp;  cudaGetSymbolAddress((void**)&w2rp,  g_W2r);
    float*  src1p; cudaGetSymbolAddress((void**)&src1p, g_src1);
    float*  dst1p; cudaGetSymbolAddress((void**)&dst1p, g_dst1);
    float*  srcpp; cudaGetSymbolAddress((void**)&srcpp, g_srcp);
    float*  dstpp; cudaGetSymbolAddress((void**)&dstpp, g_dstp);

    roundcpy_kernel<<<(NV * F1) / 1024, 256>>>(x, xrp);
    roundcpy_kernel<<<(NHEADS * F1 * FH) / 1024, 256>>>(W1, w1rp);
    roundcpy_kernel<<<(F2 * FO) / 1024, 256>>>(W2, w2rp);
    adjbits_kernel<<<(NV * NV) / 1024, 256>>>(adj);
    gemm_tf32_kernel<128, 1><<<dim3(NV / 128, NHEADS), 512, GEMM_SMEM(128, 1)>>>(
        xrp, w1rp, Wh1pp, a1, src1p, dst1p, F1, (long)F1 * FH, (long)NV * FH);
    attn_kernel<1><<<dim3(NV / 128, 1, NHEADS), 512, ATTN_SMEM>>>();
    gemm_tf32_kernel<64, 2><<<dim3(NV / 64, 2), 512, GEMM_SMEM(64, 2)>>>(
        h1p, w2rp, Wh2pp, a2, srcpp, dstpp, F2, 0L, 0L);
    srccomb_kernel<<<NV / 256, 256>>>();
    attn_kernel<4><<<dim3(NV / 128, 4), 512, ATTN_SMEM>>>();
    combine_kernel<<<NV, 256>>>(out);
}

// round 17
// speedup vs baseline: 1.3826x; 1.0089x over previous
#include <cuda_runtime.h>
#include <cuda_fp16.h>
#include <cstdint>

#define NV 4096
#define F1 512
#define FH 256
#define NHEADS 4
#define F2 1024   // nhid * nheads
#define FO 256
#define NW (NV/32) // 128 bitmask words per row

#define PSROW 36   // gemm A tile row stride (words)
#define PSTW  40   // attn P tile row stride (words; 32 used), swizzled groups
#define WBW   520  // attn Wh buf row stride (words; 512 used): 520%32==8

// ---------------- scratch (static device memory; no allocations) ------------
__device__ __align__(16) __half g_Wh1P[NHEADS * NV * FH];  // packed fp16 B-frag layout
__device__ __align__(16) float  g_h1[NV * F2];             // tf32-rounded at write
__device__ __align__(16) __half g_Wh2P[NV * FO];
__device__ __align__(16) float  g_xr[NV * F1];             // tf32-rounded x
__device__ __align__(16) float  g_W1r[NHEADS * F1 * FH];   // tf32-rounded W1
__device__ __align__(16) float  g_W2r[F2 * FO];            // tf32-rounded W2
__device__ __align__(16) float  g_src1[NHEADS * NV];
__device__ __align__(16) float  g_dst1[NHEADS * NV];
__device__ __align__(16) float  g_src2[NV];
__device__ __align__(16) float  g_dst2[NV];
__device__ __align__(16) float  g_srcp[2 * NV];          // GEMM2 col-split partials
__device__ __align__(16) float  g_dstp[2 * NV];
__device__ __align__(16) float  g_np[4 * NV * FO];       // L1 split numerators
__device__ __align__(16) float  g_lp[4 * NV];            // L1 split denominators
__device__ __align__(16) unsigned g_adjbits[NV * NW];    // 2 MB

// ---------------- helpers -----------------------------------------------------
__device__ __forceinline__ float tf32r(float x) {
    uint32_t u;
    asm("cvt.rna.tf32.f32 %0, %1;" : "=r"(u) : "f"(x));
    return __uint_as_float(u);
}
__device__ __forceinline__ float4 tf32r4(float4 v) {
    return make_float4(tf32r(v.x), tf32r(v.y), tf32r(v.z), tf32r(v.w));
}
__device__ __forceinline__ uint32_t f2h2(float a, float b) {
    __half2 h = __floats2half2_rn(a, b);
    return *reinterpret_cast<uint32_t*>(&h);
}
__device__ __forceinline__ void mma_tf32(float* d, const uint32_t* a,
                                         uint32_t b0, uint32_t b1) {
    asm volatile(
        "mma.sync.aligned.m16n8k8.row.col.f32.tf32.tf32.f32 "
        "{%0,%1,%2,%3}, {%4,%5,%6,%7}, {%8,%9}, {%0,%1,%2,%3};"
        : "+f"(d[0]), "+f"(d[1]), "+f"(d[2]), "+f"(d[3])
        : "r"(a[0]), "r"(a[1]), "r"(a[2]), "r"(a[3]), "r"(b0), "r"(b1));
}
__device__ __forceinline__ void mma_f16(float* d, const uint32_t* a,
                                        uint32_t b0, uint32_t b1) {
    asm volatile(
        "mma.sync.aligned.m16n8k16.row.col.f32.f16.f16.f32 "
        "{%0,%1,%2,%3}, {%4,%5,%6,%7}, {%8,%9}, {%0,%1,%2,%3};"
        : "+f"(d[0]), "+f"(d[1]), "+f"(d[2]), "+f"(d[3])
        : "r"(a[0]), "r"(a[1]), "r"(a[2]), "r"(a[3]), "r"(b0), "r"(b1));
}
__device__ __forceinline__ void cp16(uint32_t saddr, const void* gptr) {
    asm volatile("cp.async.cg.shared.global [%0], [%1], 16;"
                 :: "r"(saddr), "l"(gptr));
}
__device__ __forceinline__ void cp_commit() {
    asm volatile("cp.async.commit_group;");
}
__device__ __forceinline__ void cp_wait1() {
    asm volatile("cp.async.wait_group 1;");
}
// packed fp16 layout: per 32-node block, 8 group-rows of 256*(4 halves);
// node jl -> group g = (jl>>4)*4 + ((jl&7)>>1), slot = (jl&1) + ((jl>>3)&1)*2
__device__ __forceinline__ size_t packed_base(int R) {
    int blk = R >> 5, jl = R & 31;
    int g = (jl >> 4) * 4 + ((jl & 7) >> 1);
    int slot = (jl & 1) + ((jl >> 3) & 1) * 2;
    return (size_t)blk * 8192 + (size_t)g * 1024 + slot;
}

// ---------------- K-pre: RNA-round x and W1 to tf32 (fused) ------------------
__global__ void roundcpy2_kernel(const float* __restrict__ x,
                                 const float* __restrict__ W1) {
    const int i = (blockIdx.x * blockDim.x + threadIdx.x) * 4;
    if (i < NV * F1) {
        *(float4*)(g_xr + i) = tf32r4(*(const float4*)(x + i));
    } else {
        const int j = i - NV * F1;
        *(float4*)(g_W1r + j) = tf32r4(*(const float4*)(W1 + j));
    }
}
__global__ void roundcpy_kernel(const float* __restrict__ in,
                                float* __restrict__ out) {
    const int i = (blockIdx.x * blockDim.x + threadIdx.x) * 4;
    *(float4*)(out + i) = tf32r4(*(const float4*)(in + i));
}

// ---------------- K0: adjacency -> bitmask (MLP=4) ----------------------------
__global__ void adjbits_kernel(const int* __restrict__ adj) {
    const int base = blockIdx.x * 1024 + threadIdx.x;
#pragma unroll
    for (int k = 0; k < 4; k++) {
        const int idx = base + k * 256;
        unsigned bit = (adj[idx] != 0) ? 1u : 0u;
        unsigned w = __ballot_sync(0xffffffffu, bit);
        if ((threadIdx.x & 31) == 0) g_adjbits[idx >> 5] = w;
    }
}

// ---------------- K1: tf32 mma GEMM + fused src/dst, cp.async pipeline -------
// Inputs are pre-rounded tf32 -> HW truncation in MMA is exact (== RNA).
// CSPLIT=1: blockIdx.y = head. CSPLIT=2: blockIdx.y = column half (GEMM2),
// src/dst written as per-half partials (combined by srccomb_kernel).
template <int ROWS, int CSPLIT>
__global__ void __launch_bounds__(512, 1)
gemm_tf32_kernel(const float* __restrict__ A, const float* __restrict__ B,
                 __half* __restrict__ Cp, const float* __restrict__ avec,
                 float* __restrict__ src, float* __restrict__ dst,
                 int K, long bStride, long cStride) {
    constexpr int MT  = ROWS / 64;
    constexpr int TPR = 512 / ROWS;       // threads per A-row (4 or 8)
    constexpr int AK  = 32 / TPR;         // A cols per thread (8 or 4)
    constexpr int NCOLS = 256 / CSPLIT;   // output cols per CTA
    constexpr int NT  = NCOLS / 32;       // n-tiles per warp (8 or 4)
    constexpr int BST = NCOLS + 8;        // B tile stride: =8 (mod 32)
    constexpr int BQ  = NCOLS / 64;       // B float4 chunks per thread
    extern __shared__ char smem[];
    float* As  = (float*)smem;                            // [3][ROWS*PSROW]
    float* Bs  = (float*)(smem + 3 * ROWS * PSROW * 4);   // [3][32*BST]
    float* sa  = (float*)(smem + 3 * ROWS * PSROW * 4 + 3 * 32 * BST * 4);
    float* lsm = sa + 2 * FH;                             // [ROWS][8]
    const uint32_t as_s = (uint32_t)__cvta_generic_to_shared(As);
    const uint32_t bs_s = (uint32_t)__cvta_generic_to_shared(Bs);

    const int tid = threadIdx.x;
    const int wid = tid >> 5, lane = tid & 31;
    const int wr = wid >> 2, wc = wid & 3;
    const int b  = (CSPLIT > 1) ? 0 : blockIdx.y;
    const int cs = (CSPLIT > 1) ? blockIdx.y : 0;
    const int coloff = cs * NCOLS;
    const float* Bb = B + (size_t)b * bStride;
    __half* Cpb = Cp + (size_t)b * cStride;
    const float* av = avec + (size_t)b * 2 * FH;
    float* srcb = src + (size_t)((CSPLIT > 1) ? cs : b) * NV;
    float* dstb = dst + (size_t)((CSPLIT > 1) ? cs : b) * NV;
    const int i0 = blockIdx.x * ROWS;

    sa[tid] = av[tid];   // 512 threads load 2*FH floats

    const int arow = tid / TPR, ak0 = (tid % TPR) * AK;
    const int jrow = tid >> 4, fbase = (tid & 15) * 4;
    const int ar = lane >> 2, ak = lane & 3;

    float d[MT][NT][4];
#pragma unroll
    for (int mt = 0; mt < MT; mt++)
#pragma unroll
        for (int nt = 0; nt < NT; nt++)
#pragma unroll
            for (int v = 0; v < 4; v++) d[mt][nt][v] = 0.f;

    const int NKT = K / 32;

#define G_ISSUE(kt_, buf_)                                                    \
    {                                                                         \
        const float* bp_ = Bb + (size_t)((kt_) * 32 + jrow) * FH + coloff + fbase; \
        const uint32_t bd_ = bs_s +                                           \
            (uint32_t)((buf_) * 32 * BST + jrow * BST + fbase) * 4u;          \
        _Pragma("unroll")                                                     \
        for (int q_ = 0; q_ < BQ; q_++)                                       \
            cp16(bd_ + q_ * 64u * 4u, bp_ + 64 * q_);                         \
        const float* ap_ = A + (size_t)(i0 + arow) * K + (kt_) * 32 + ak0;    \
        const uint32_t ad_ = as_s +                                           \
            (uint32_t)((buf_) * ROWS * PSROW + arow * PSROW + ak0) * 4u;      \
        _Pragma("unroll")                                                     \
        for (int q_ = 0; q_ < AK / 4; q_++)                                   \
            cp16(ad_ + q_ * 16u, ap_ + q_ * 4);                               \
    }

    G_ISSUE(0, 0); cp_commit();
    G_ISSUE(1, 1); cp_commit();

    for (int kt = 0; kt < NKT; kt++) {
        cp_wait1();
        __syncthreads();
        if (kt + 2 < NKT) { G_ISSUE(kt + 2, (kt + 2) % 3); }
        cp_commit();
        const float* pB = As + (kt % 3) * ROWS * PSROW;
        const float* wB = Bs + (kt % 3) * 32 * BST;
#pragma unroll
        for (int kk = 0; kk < 4; kk++) {
            const int k0 = kk * 8;
            uint32_t a[MT][4];
#pragma unroll
            for (int mt = 0; mt < MT; mt++) {
                const float* pr = pB + (wr * 16 * MT + mt * 16 + ar) * PSROW + k0 + ak;
                a[mt][0] = __float_as_uint(pr[0]);
                a[mt][1] = __float_as_uint(pr[8 * PSROW]);
                a[mt][2] = __float_as_uint(pr[4]);
                a[mt][3] = __float_as_uint(pr[8 * PSROW + 4]);
            }
#pragma unroll
            for (int nt = 0; nt < NT; nt++) {
                const int n = wc * (NT * 8) + nt * 8 + ar;
                uint32_t b0 = __float_as_uint(wB[(k0 + ak) * BST + n]);
                uint32_t b1 = __float_as_uint(wB[(k0 + ak + 4) * BST + n]);
#pragma unroll
                for (int mt = 0; mt < MT; mt++)
                    mma_tf32(d[mt][nt], a[mt], b0, b1);
            }
        }
    }
#undef G_ISSUE
    __syncthreads();
    // ---- epilogue: packed fp16 store + fused src/dst (partial if CSPLIT>1) ----
#pragma unroll
    for (int mt = 0; mt < MT; mt++) {
        const int r0 = wr * 16 * MT + mt * 16 + ar;
        const int r1 = r0 + 8;
        const int R0 = i0 + r0, R1 = i0 + r1;
        const size_t pb0 = packed_base(R0), pb1 = packed_base(R1);
        float s10 = 0.f, s20 = 0.f, s11 = 0.f, s21 = 0.f;
#pragma unroll
        for (int nt = 0; nt < NT; nt++) {
            const int cl = wc * (NT * 8) + nt * 8 + 2 * ak;
            const int c  = coloff + cl;
            float t0 = d[mt][nt][0], t1 = d[mt][nt][1];
            float t2 = d[mt][nt][2], t3 = d[mt][nt][3];
            Cpb[pb0 + (size_t)c * 4]       = __float2half_rn(t0);
            Cpb[pb0 + (size_t)(c + 1) * 4] = __float2half_rn(t1);
            Cpb[pb1 + (size_t)c * 4]       = __float2half_rn(t2);
            Cpb[pb1 + (size_t)(c + 1) * 4] = __float2half_rn(t3);
            s10 += t0 * sa[c] + t1 * sa[c + 1];
            s20 += t0 * sa[FH + c] + t1 * sa[FH + c + 1];
            s11 += t2 * sa[c] + t3 * sa[c + 1];
            s21 += t2 * sa[FH + c] + t3 * sa[FH + c + 1];
        }
        s10 += __shfl_down_sync(0xffffffffu, s10, 2);
        s10 += __shfl_down_sync(0xffffffffu, s10, 1);
        s20 += __shfl_down_sync(0xffffffffu, s20, 2);
        s20 += __shfl_down_sync(0xffffffffu, s20, 1);
        s11 += __shfl_down_sync(0xffffffffu, s11, 2);
        s11 += __shfl_down_sync(0xffffffffu, s11, 1);
        s21 += __shfl_down_sync(0xffffffffu, s21, 2);
        s21 += __shfl_down_sync(0xffffffffu, s21, 1);
        if (ak == 0) {
            lsm[r0 * 8 + wc * 2]     = s10;
            lsm[r0 * 8 + wc * 2 + 1] = s20;
            lsm[r1 * 8 + wc * 2]     = s11;
            lsm[r1 * 8 + wc * 2 + 1] = s21;
        }
    }
    __syncthreads();
    if (tid < ROWS) {
        float s1 = lsm[tid*8] + lsm[tid*8+2] + lsm[tid*8+4] + lsm[tid*8+6];
        float s2 = lsm[tid*8+1] + lsm[tid*8+3] + lsm[tid*8+5] + lsm[tid*8+7];
        srcb[i0 + tid] = s1;
        dstb[i0 + tid] = s2;
    }
}

#define GEMM_SMEM(R, CS) (3 * (R) * PSROW * 4 + 3 * 32 * (256 / (CS) + 8) * 4 + \
                          512 * 4 + (R) * 8 * 4)

// ---------------- K1b: combine GEMM2 src/dst partials ------------------------
__global__ void srccomb_kernel() {
    const int i = blockIdx.x * blockDim.x + threadIdx.x;
    g_src2[i] = g_srcp[i] + g_srcp[NV + i];
    g_dst2[i] = g_dstp[i] + g_dstp[NV + i];
}

// ---------------- K3: fp16 mma fused attention, KT=64 per phase --------------
// (R11-proven structure) 128x256 tile, 512 threads, 16 warps (4x4),
// per-SMSP phase stagger, 64 neighbors/barrier, 3-buffer cp.async depth-2.
// L0 writes g_h1 tf32-rounded (consumed raw by gemm2's cp.async path).
#define ATTN_SMEM (2 * 128 * PSTW * 4 + 3 * 16 * WBW * 4 + 512 * 4)

template <int NSPLIT>
__global__ void __launch_bounds__(512, 1)
attn_kernel() {
    extern __shared__ char smem[];
    float* Ps    = (float*)smem;                          // [2][128*PSTW]
    float* Whs   = (float*)(smem + 2 * 128 * PSTW * 4);   // [3][16*WBW]
    float* lpart = (float*)(smem + 2 * 128 * PSTW * 4 + 3 * 16 * WBW * 4);
    const uint32_t whs_s = (uint32_t)__cvta_generic_to_shared(Whs);

    const int tid = threadIdx.x;
    const int wid = tid >> 5, lane = tid & 31;
    const int wr = wid >> 2, wc = wid & 3;
    const int i0 = blockIdx.x * 128;
    const bool mmaFirst = ((wid >> 2) & 1) != 0;   // per-SMSP 2/2 split

    const __half* WhP; const float* srcT; const float* dR;
    int jbase, NKT;
    if (NSPLIT > 1) {
        WhP = g_Wh2P; srcT = g_src2; dR = g_dst2;
        jbase = blockIdx.y * (NV / NSPLIT);
        NKT = (NV / NSPLIT) / 64;
    } else {
        const int b = blockIdx.z;
        WhP = g_Wh1P + (size_t)b * NV * FH;
        srcT = g_src1 + b * NV; dR = g_dst1 + b * NV;
        jbase = 0; NKT = NV / 64;
    }

    const int prow = tid >> 2;          // 0..127
    const int q_   = tid & 3;
    const float si = srcT[i0 + prow];
    const unsigned* adjrow = g_adjbits + (size_t)(i0 + prow) * NW + (jbase >> 5);
    const int ar = lane >> 2, ak = lane & 3;

    // cp.async mapping: thread -> (group row tid>>5 of 16, chunk tid&31)
    const __half* wsrc0 = WhP + (size_t)(jbase >> 5) * 8192 +
                          (size_t)(tid >> 5) * 1024 + (size_t)(tid & 31) * 8;
    const uint32_t wdst0 = whs_s +
                           (uint32_t)((tid >> 5) * WBW + (tid & 31) * 4) * 4u;

    float d[2][8][4];
#pragma unroll
    for (int mt = 0; mt < 2; mt++)
#pragma unroll
        for (int nt = 0; nt < 8; nt++)
#pragma unroll
            for (int v = 0; v < 4; v++) d[mt][nt][v] = 0.f;
    float lsum = 0.f;

    const int kb_ = (q_ < 2) ? 4 * q_ : 4 * q_ + 8;   // 0,4,16,20
    const int s_  = prow & 7;

#define COMPUTE_P(kt_, pbuf_)                                                 \
    {                                                                         \
        uint2* pr_ = (uint2*)((pbuf_) + prow * PSTW);                         \
        _Pragma("unroll")                                                     \
        for (int h_ = 0; h_ < 2; h_++) {                                      \
            const int j0_ = jbase + (kt_) * 64 + 32 * h_;                     \
            const unsigned aw_ = adjrow[2 * (kt_) + h_];                      \
            float4 dv1 = *(const float4*)(dR + j0_ + kb_);                    \
            float4 dv2 = *(const float4*)(dR + j0_ + kb_ + 8);                \
            float dd_[8] = {dv1.x, dv1.y, dv1.z, dv1.w,                       \
                            dv2.x, dv2.y, dv2.z, dv2.w};                      \
            float p_[8];                                                      \
            _Pragma("unroll")                                                 \
            for (int u_ = 0; u_ < 8; u_++) {                                  \
                float e_ = si + dd_[u_];                                      \
                e_ = fmaxf(e_, 0.2f * e_);                                    \
                float pp_ = __expf(e_);                                       \
                pp_ = fminf(pp_, 65000.f);                                    \
                const int bit_ = kb_ + ((u_ < 4) ? u_ : u_ + 4);              \
                pp_ = ((aw_ >> bit_) & 1u) ? pp_ : 0.f;                       \
                lsum += pp_;                                                  \
                p_[u_] = pp_;                                                 \
            }                                                                 \
            const int g0_ = 2 * q_;                                           \
            pr_[8 * h_ + (g0_ ^ s_)] =                                        \
                make_uint2(f2h2(p_[0], p_[1]), f2h2(p_[4], p_[5]));           \
            pr_[8 * h_ + ((g0_ + 1) ^ s_)] =                                  \
                make_uint2(f2h2(p_[2], p_[3]), f2h2(p_[6], p_[7]));           \
        }                                                                     \
    }

#define ISSUE_WH(kt_, buf_)                                                   \
    {                                                                         \
        const __half* wp_ = wsrc0 + (size_t)(kt_) * 16384;                    \
        const uint32_t wd_ = wdst0 + (uint32_t)(buf_) * (16u * WBW * 4u);     \
        _Pragma("unroll")                                                     \
        for (int q2_ = 0; q2_ < 4; q2_++)                                     \
            cp16(wd_ + q2_ * 512u, wp_ + q2_ * 256);                          \
    }

#define PREP_STEP(kt_)                                                        \
    {                                                                         \
        if ((kt_) + 2 < NKT) { ISSUE_WH((kt_) + 2, ((kt_) + 2) % 3); }        \
        cp_commit();                                                          \
        if ((kt_) + 1 < NKT) {                                                \
            COMPUTE_P((kt_) + 1, Ps + (((kt_) + 1) & 1) * 128 * PSTW);        \
        }                                                                     \
    }

#define MMA_STEP(kt_)                                                         \
    {                                                                         \
        const float* pB = Ps + ((kt_) & 1) * 128 * PSTW;                      \
        const float* wB = Whs + ((kt_) % 3) * 16 * WBW;                       \
        _Pragma("unroll")                                                     \
        for (int kk = 0; kk < 4; kk++) {                                      \
            const int gi_ = kk * 4 + ak;                                      \
            const int idx_ = (gi_ & 8) | ((gi_ & 7) ^ ar);                    \
            uint32_t a[2][4];                                                 \
            _Pragma("unroll")                                                 \
            for (int mt = 0; mt < 2; mt++) {                                  \
                const int row_ = wr * 32 + mt * 16 + ar;                      \
                uint2 u_ = ((const uint2*)(pB + row_ * PSTW))[idx_];          \
                uint2 v_ = ((const uint2*)(pB + (row_ + 8) * PSTW))[idx_];    \
                a[mt][0] = u_.x; a[mt][1] = v_.x;                             \
                a[mt][2] = u_.y; a[mt][3] = v_.y;                             \
            }                                                                 \
            _Pragma("unroll")                                                 \
            for (int nt = 0; nt < 8; nt++) {                                  \
                const int n = wc * 64 + nt * 8 + ar;                          \
                uint2 b_ = ((const uint2*)(wB + gi_ * WBW))[n];               \
                _Pragma("unroll")                                             \
                for (int mt = 0; mt < 2; mt++)                                \
                    mma_f16(d[mt][nt], a[mt], b_.x, b_.y);                    \
            }                                                                 \
        }                                                                     \
    }

    // ---- prologue ----
    ISSUE_WH(0, 0); cp_commit();
    if (1 < NKT) { ISSUE_WH(1, 1); }
    cp_commit();
    COMPUTE_P(0, Ps);

    for (int kt = 0; kt < NKT; kt++) {
        cp_wait1();          // Wh(kt) complete (per-thread)
        __syncthreads();     // visibility; prev MMA reads done
        if (mmaFirst) {
            MMA_STEP(kt);
            PREP_STEP(kt);
        } else {
            PREP_STEP(kt);
            MMA_STEP(kt);
        }
    }
    __syncthreads();
    lpart[tid] = lsum;       // lpart[prow*4 + q]
    __syncthreads();

    if (NSPLIT > 1) {
        float* np = g_np + (size_t)blockIdx.y * NV * FO;
#pragma unroll
        for (int mt = 0; mt < 2; mt++) {
            const int r0 = wr * 32 + mt * 16 + ar;
            const int r1 = r0 + 8;
#pragma unroll
            for (int nt = 0; nt < 8; nt++) {
                const int c = wc * 64 + nt * 8 + 2 * ak;
                *(float2*)(np + (size_t)(i0 + r0) * FO + c) = make_float2(d[mt][nt][0], d[mt][nt][1]);
                *(float2*)(np + (size_t)(i0 + r1) * FO + c) = make_float2(d[mt][nt][2], d[mt][nt][3]);
            }
        }
        if (tid < 128) {
            float l = lpart[tid * 4] + lpart[tid * 4 + 1] +
                      lpart[tid * 4 + 2] + lpart[tid * 4 + 3];
            g_lp[blockIdx.y * NV + i0 + tid] = l;
        }
    } else {
        float* out = g_h1;
        const int coloff = blockIdx.z * FH;
#pragma unroll
        for (int mt = 0; mt < 2; mt++) {
            const int r0 = wr * 32 + mt * 16 + ar;
            const int r1 = r0 + 8;
            const float l0 = lpart[r0*4] + lpart[r0*4+1] + lpart[r0*4+2] + lpart[r0*4+3];
            const float l1 = lpart[r1*4] + lpart[r1*4+1] + lpart[r1*4+2] + lpart[r1*4+3];
            const float rl0 = 1.0f / l0, rl1 = 1.0f / l1;
#pragma unroll
            for (int nt = 0; nt < 8; nt++) {
                const int c = coloff + wc * 64 + nt * 8 + 2 * ak;
                float o0 = d[mt][nt][0] * rl0, o1 = d[mt][nt][1] * rl0;
                float o2 = d[mt][nt][2] * rl1, o3 = d[mt][nt][3] * rl1;
                o0 = o0 > 0.f ? o0 : (__expf(o0) - 1.0f);
                o1 = o1 > 0.f ? o1 : (__expf(o1) - 1.0f);
                o2 = o2 > 0.f ? o2 : (__expf(o2) - 1.0f);
                o3 = o3 > 0.f ? o3 : (__expf(o3) - 1.0f);
                *(float2*)(out + (size_t)(i0 + r0) * F2 + c) =
                    make_float2(tf32r(o0), tf32r(o1));
                *(float2*)(out + (size_t)(i0 + r1) * F2 + c) =
                    make_float2(tf32r(o2), tf32r(o3));
            }
        }
    }
#undef COMPUTE_P
#undef ISSUE_WH
#undef PREP_STEP
#undef MMA_STEP
}

// ---------------- K4: combine 4 split partials (layer 1 epilogue) ------------
__global__ void combine_kernel(float* __restrict__ out) {
    const int i = blockIdx.x;
    const int c = threadIdx.x;
    float l = 0.f, n = 0.f;
#pragma unroll
    for (int s = 0; s < 4; s++) {
        l += g_lp[s * NV + i];
        n += g_np[(size_t)s * NV * FO + (size_t)i * FO + c];
    }
    out[(size_t)i * FO + c] = n / l;
}

// ---------------- launch -----------------------------------------------------
extern "C" void kernel_launch(void* const* d_in, const int* in_sizes, int n_in,
                              void* d_out, int out_size) {
    (void)in_sizes; (void)n_in; (void)out_size;
    const float* x   = (const float*)d_in[0];
    const int*   adj = (const int*)d_in[1];
    const float* W1  = (const float*)d_in[2];
    const float* a1  = (const float*)d_in[3];
    const float* W2  = (const float*)d_in[4];
    const float* a2  = (const float*)d_in[5];
    float* out = (float*)d_out;

    static int inited = 0;
    static cudaStream_t s2;
    static cudaEvent_t evFork, evSide;
    if (!inited) {
        cudaFuncSetAttribute(gemm_tf32_kernel<128, 1>,
            cudaFuncAttributeMaxDynamicSharedMemorySize, GEMM_SMEM(128, 1));
        cudaFuncSetAttribute(gemm_tf32_kernel<64, 2>,
            cudaFuncAttributeMaxDynamicSharedMemorySize, GEMM_SMEM(64, 2));
        cudaFuncSetAttribute(attn_kernel<1>,
            cudaFuncAttributeMaxDynamicSharedMemorySize, ATTN_SMEM);
        cudaFuncSetAttribute(attn_kernel<4>,
            cudaFuncAttributeMaxDynamicSharedMemorySize, ATTN_SMEM);
        cudaStreamCreateWithFlags(&s2, cudaStreamNonBlocking);
        cudaEventCreateWithFlags(&evFork, cudaEventDisableTiming);
        cudaEventCreateWithFlags(&evSide, cudaEventDisableTiming);
        inited = 1;
    }

    __half* Wh1pp; cudaGetSymbolAddress((void**)&Wh1pp, g_Wh1P);
    __half* Wh2pp; cudaGetSymbolAddress((void**)&Wh2pp, g_Wh2P);
    float*  h1p;   cudaGetSymbolAddress((void**)&h1p,   g_h1);
    float*  xrp;   cudaGetSymbolAddress((void**)&xrp,   g_xr);
    float*  w1rp;  cudaGetSymbolAddress((void**)&w1rp,  g_W1r);
    float*  w2rp;  cudaGetSymbolAddress((void**)&w2rp,  g_W2r);
    float*  src1p; cudaGetSymbolAddress((void**)&src1p, g_src1);
    float*  dst1p; cudaGetSymbolAddress((void**)&dst1p, g_dst1);
    float*  srcpp; cudaGetSymbolAddress((void**)&srcpp, g_srcp);
    float*  dstpp; cudaGetSymbolAddress((void**)&dstpp, g_dstp);

    // fork: side stream does adjbits + W2 rounding, overlapped with
    // x/W1 rounding + gemm1 on the main stream.
    cudaEventRecord(evFork, 0);
    cudaStreamWaitEvent(s2, evFork, 0);
    adjbits_kernel<<<(NV * NV) / 1024, 256, 0, s2>>>(adj);
    roundcpy_kernel<<<(F2 * FO) / 1024, 256, 0, s2>>>(W2, w2rp);
    cudaEventRecord(evSide, s2);

    roundcpy2_kernel<<<(NV * F1 + NHEADS * F1 * FH) / 1024, 256>>>(x, W1);
    gemm_tf32_kernel<128, 1><<<dim3(NV / 128, NHEADS), 512, GEMM_SMEM(128, 1)>>>(
        xrp, w1rp, Wh1pp, a1, src1p, dst1p, F1, (long)F1 * FH, (long)NV * FH);

    cudaStreamWaitEvent(0, evSide, 0);   // join before attention
    attn_kernel<1><<<dim3(NV / 128, 1, NHEADS), 512, ATTN_SMEM>>>();
    gemm_tf32_kernel<64, 2><<<dim3(NV / 64, 2), 512, GEMM_SMEM(64, 2)>>>(
        h1p, w2rp, Wh2pp, a2, srcpp, dstpp, F2, 0L, 0L);
    srccomb_kernel<<<NV / 256, 256>>>();
    attn_kernel<4><<<dim3(NV / 128, 4), 512, ATTN_SMEM>>>();
    combine_kernel<<<NV, 256>>>(out);
}